// round 1
// baseline (speedup 1.0000x reference)
#include <cuda_runtime.h>
#include <math.h>

#define Bv 8
#define Lv 512
#define Kv 30
#define Hv 128
#define NINv 384
#define NPTSv 8
#define FEATv 72
#define MSGV 456           // 384 (h_E) + 72 (geom feats): W1 rows 128..583
#define EPSv 1e-8f

// scratch for per-edge geometric features (35.4 MB) — static device array, no allocs
__device__ float g_feat[(size_t)Bv * Lv * Kv * FEATv];

__device__ __forceinline__ float geluf(float x) {
    return 0.5f * x * (1.0f + erff(x * 0.7071067811865476f));
}

// Build frame: R columns = [e0 e1 e2] stored row-major R[i*3+j] = e_j[i]; t = CA
__device__ __forceinline__ void make_frame(const float* __restrict__ x,
                                           float* __restrict__ R,
                                           float* __restrict__ t) {
    float Nx = x[0], Ny = x[1], Nz = x[2];
    float CAx = x[3], CAy = x[4], CAz = x[5];
    float Cx = x[6], Cy = x[7], Cz = x[8];
    float e0x = CAx - Nx, e0y = CAy - Ny, e0z = CAz - Nz;
    float inv = 1.0f / sqrtf(e0x * e0x + e0y * e0y + e0z * e0z + EPSv);
    e0x *= inv; e0y *= inv; e0z *= inv;
    float e1x = Cx - CAx, e1y = Cy - CAy, e1z = Cz - CAz;
    float d = e0x * e1x + e0y * e1y + e0z * e1z;
    e1x -= e0x * d; e1y -= e0y * d; e1z -= e0z * d;
    inv = 1.0f / sqrtf(e1x * e1x + e1y * e1y + e1z * e1z + EPSv);
    e1x *= inv; e1y *= inv; e1z *= inv;
    float e2x = e0y * e1z - e0z * e1y;
    float e2y = e0z * e1x - e0x * e1z;
    float e2z = e0x * e1y - e0y * e1x;
    R[0] = e0x; R[1] = e1x; R[2] = e2x;
    R[3] = e0y; R[4] = e1y; R[5] = e2y;
    R[6] = e0z; R[7] = e1z; R[8] = e2z;
    t[0] = CAx; t[1] = CAy; t[2] = CAz;
}

// ---------------------------------------------------------------------------
// Kernel 1: per-edge geometry features -> g_feat[edge][72]
// feat layout: [ple(24), pln(8), npl(24), npl_norm(8), npg_norm(8)]
// One block per (b,l); 4 warps each handle k = warp, warp+4, ...
// ---------------------------------------------------------------------------
__global__ void __launch_bounds__(128) geo_kernel(
    const float* __restrict__ hE,
    const float* __restrict__ Xn,
    const float* __restrict__ Wp,
    const float* __restrict__ bp)
{
    int bl = blockIdx.x;
    int tid = threadIdx.x;
    int w = tid >> 5, lane = tid & 31;

    __shared__ float s_hvp0[128];
    __shared__ float s_hvp[4][128];
    __shared__ float s_R[4][9], s_t[4][3], s_pl[4][24], s_npg[4][24];
    __shared__ float s_R0[9], s_t0[3], s_plocal[24], s_plnv[8], s_pglob[24];

    // ---- phase 0: edge k = 0 (reference quantities) ----
    const float* hE0 = hE + ((size_t)bl * Kv) * NINv;
    s_hvp0[tid] = hE0[256 + tid];           // h_V_prev = h_E[..., -128:]
    if (tid == 0) {
        make_frame(Xn + ((size_t)bl * Kv) * 9, s_R0, s_t0);
    }
    __syncthreads();
    if (tid < 24) {
        float acc = bp[tid];
        #pragma unroll 4
        for (int i = 0; i < 128; i++) acc += s_hvp0[i] * Wp[i * 24 + tid];
        s_plocal[tid] = acc;                 // p_local = p_ln[k=0]
    }
    __syncthreads();
    if (tid < 8) {
        float a = s_plocal[tid * 3], b = s_plocal[tid * 3 + 1], cc = s_plocal[tid * 3 + 2];
        s_plnv[tid] = sqrtf(a * a + b * b + cc * cc + EPSv);
    }
    if (tid < 24) {
        int n = tid / 3, i = tid % 3;
        float v = s_t0[i];
        #pragma unroll
        for (int j = 0; j < 3; j++) v += s_R0[i * 3 + j] * s_plocal[n * 3 + j];
        s_pglob[tid] = v;                    // p_global = npg[k=0]
    }
    __syncthreads();

    // ---- phase 1: all edges ----
    for (int k = w; k < Kv; k += 4) {
        const float* hEk = hE + ((size_t)bl * Kv + k) * NINv;
        for (int i = lane; i < 128; i += 32) s_hvp[w][i] = hEk[256 + i];
        if (lane == 0) make_frame(Xn + ((size_t)bl * Kv + k) * 9, s_R[w], s_t[w]);
        __syncwarp();
        if (lane < 24) {
            float acc = bp[lane];
            #pragma unroll 4
            for (int i = 0; i < 128; i++) acc += s_hvp[w][i] * Wp[i * 24 + lane];
            s_pl[w][lane] = acc;
        }
        __syncwarp();
        if (lane < 24) {
            int n = lane / 3, i = lane % 3;
            float v = s_t[w][i];
            #pragma unroll
            for (int j = 0; j < 3; j++) v += s_R[w][i * 3 + j] * s_pl[w][n * 3 + j];
            s_npg[w][lane] = v;
        }
        __syncwarp();
        float* fo = g_feat + ((size_t)bl * Kv + k) * FEATv;
        if (lane < 24) fo[lane] = s_plocal[lane];
        if (lane < 8)  fo[24 + lane] = s_plnv[lane];
        if (lane < 24) {
            int n = lane / 3, i = lane % 3;
            float v = 0.0f;
            #pragma unroll
            for (int j = 0; j < 3; j++)
                v += s_R0[j * 3 + i] * (s_npg[w][n * 3 + j] - s_t0[j]);  // R0^T
            fo[32 + lane] = v;
            s_pl[w][lane] = v;  // reuse buffer for npl (p_ln no longer needed)
        }
        __syncwarp();
        if (lane < 8) {
            float a = s_pl[w][lane * 3], b = s_pl[w][lane * 3 + 1], cc = s_pl[w][lane * 3 + 2];
            fo[56 + lane] = sqrtf(a * a + b * b + cc * cc + EPSv);
            float dx = s_pglob[lane * 3]     - s_npg[w][lane * 3];
            float dy = s_pglob[lane * 3 + 1] - s_npg[w][lane * 3 + 1];
            float dz = s_pglob[lane * 3 + 2] - s_npg[w][lane * 3 + 2];
            fo[64 + lane] = sqrtf(dx * dx + dy * dy + dz * dz + EPSv);
        }
        __syncwarp();
    }
}

// ---------------------------------------------------------------------------
// Kernel 2: fused GEMM chain + masked mean + LN1 + FFN + LN2 + output
// One block per (b,l); 128 threads; thread c owns output column c for all 30 k
// ---------------------------------------------------------------------------
extern __shared__ float sm[];
__global__ void __launch_bounds__(128) main_kernel(
    const float* __restrict__ hV, const float* __restrict__ hE,
    const float* __restrict__ maskV, const float* __restrict__ maskA,
    const float* __restrict__ W1, const float* __restrict__ b1,
    const float* __restrict__ W2, const float* __restrict__ b2,
    const float* __restrict__ W3, const float* __restrict__ b3,
    const float* __restrict__ Wi, const float* __restrict__ bi,
    const float* __restrict__ Wo, const float* __restrict__ bo,
    const float* __restrict__ g1, const float* __restrict__ be1,
    const float* __restrict__ g2, const float* __restrict__ be2,
    float* __restrict__ out)
{
    int bl = blockIdx.x;
    int c = threadIdx.x;

    float* s_msg = sm;            // 30*456 = 13680
    float* s_y   = sm + 13680;    // 30*128 = 3840
    float* s_hv  = sm + 17520;    // 128
    float* s_h   = sm + 17648;    // 128
    float* s_hi  = sm + 17776;    // 512
    float* s_red = sm + 18288;    // 16

    // stage msg tile (h_E part + feat part) and h_V
    {
        const float* src = hE + (size_t)bl * Kv * NINv;
        for (int idx = c; idx < Kv * NINv; idx += 128) {
            int k = idx / NINv, r = idx - k * NINv;
            s_msg[k * MSGV + r] = src[idx];
        }
        const float* fsrc = g_feat + (size_t)bl * Kv * FEATv;
        for (int idx = c; idx < Kv * FEATv; idx += 128) {
            int k = idx / FEATv, r = idx - k * FEATv;
            s_msg[k * MSGV + NINv + r] = fsrc[idx];
        }
        s_hv[c] = hV[(size_t)bl * Hv + c];
    }
    __syncthreads();

    float acc[Kv];
    // node (h_V) contribution: identical across k
    {
        float base = b1[c];
        #pragma unroll 4
        for (int r = 0; r < Hv; r++) base = fmaf(s_hv[r], W1[r * Hv + c], base);
        #pragma unroll
        for (int k = 0; k < Kv; k++) acc[k] = base;
    }
    // edge-varying part of msg @ W1
    for (int r = 0; r < MSGV; r += 4) {
        float w0 = W1[(Hv + r) * Hv + c];
        float w1 = W1[(Hv + r + 1) * Hv + c];
        float w2 = W1[(Hv + r + 2) * Hv + c];
        float w3 = W1[(Hv + r + 3) * Hv + c];
        #pragma unroll
        for (int k = 0; k < Kv; k++) {
            float4 m = *(const float4*)(s_msg + k * MSGV + r);
            acc[k] = fmaf(m.x, w0, fmaf(m.y, w1, fmaf(m.z, w2, fmaf(m.w, w3, acc[k]))));
        }
    }
    #pragma unroll
    for (int k = 0; k < Kv; k++) s_y[k * Hv + c] = geluf(acc[k]);
    __syncthreads();

    // layer 2
    #pragma unroll
    for (int k = 0; k < Kv; k++) acc[k] = b2[c];
    for (int r = 0; r < Hv; r += 4) {
        float w0 = W2[r * Hv + c],       w1 = W2[(r + 1) * Hv + c];
        float w2 = W2[(r + 2) * Hv + c], w3 = W2[(r + 3) * Hv + c];
        #pragma unroll
        for (int k = 0; k < Kv; k++) {
            float4 m = *(const float4*)(s_y + k * Hv + r);
            acc[k] = fmaf(m.x, w0, fmaf(m.y, w1, fmaf(m.z, w2, fmaf(m.w, w3, acc[k]))));
        }
    }
    __syncthreads();
    #pragma unroll
    for (int k = 0; k < Kv; k++) s_y[k * Hv + c] = geluf(acc[k]);
    __syncthreads();

    // layer 3 + masked mean over k
    #pragma unroll
    for (int k = 0; k < Kv; k++) acc[k] = b3[c];
    for (int r = 0; r < Hv; r += 4) {
        float w0 = W3[r * Hv + c],       w1 = W3[(r + 1) * Hv + c];
        float w2 = W3[(r + 2) * Hv + c], w3 = W3[(r + 3) * Hv + c];
        #pragma unroll
        for (int k = 0; k < Kv; k++) {
            float4 m = *(const float4*)(s_y + k * Hv + r);
            acc[k] = fmaf(m.x, w0, fmaf(m.y, w1, fmaf(m.z, w2, fmaf(m.w, w3, acc[k]))));
        }
    }
    float nodem = 0.0f;
    #pragma unroll
    for (int k = 0; k < Kv; k++) nodem += acc[k] * maskA[bl * Kv + k];
    nodem *= (1.0f / (float)Kv);

    // ---- LN1 ----
    float xv = s_hv[c] + nodem;
    float s = xv, q = xv * xv;
    #pragma unroll
    for (int o = 16; o; o >>= 1) {
        s += __shfl_xor_sync(0xffffffffu, s, o);
        q += __shfl_xor_sync(0xffffffffu, q, o);
    }
    if ((c & 31) == 0) { s_red[c >> 5] = s; s_red[8 + (c >> 5)] = q; }
    __syncthreads();
    s = s_red[0] + s_red[1] + s_red[2] + s_red[3];
    q = s_red[8] + s_red[9] + s_red[10] + s_red[11];
    float mean = s * (1.0f / (float)Hv);
    float var  = q * (1.0f / (float)Hv) - mean * mean;
    float h1 = (xv - mean) * rsqrtf(var + 1e-5f) * g1[c] + be1[c];
    s_h[c] = h1;
    __syncthreads();

    // ---- FFN: gelu(h @ Wi + bi) @ Wo + bo ----
    float hi0 = bi[c], hi1 = bi[c + 128], hi2 = bi[c + 256], hi3 = bi[c + 384];
    #pragma unroll 4
    for (int r = 0; r < Hv; r++) {
        float hr = s_h[r];
        const float* wrow = Wi + r * 512;
        hi0 = fmaf(hr, wrow[c],       hi0);
        hi1 = fmaf(hr, wrow[c + 128], hi1);
        hi2 = fmaf(hr, wrow[c + 256], hi2);
        hi3 = fmaf(hr, wrow[c + 384], hi3);
    }
    s_hi[c]       = geluf(hi0);
    s_hi[c + 128] = geluf(hi1);
    s_hi[c + 256] = geluf(hi2);
    s_hi[c + 384] = geluf(hi3);
    __syncthreads();
    float dv = bo[c];
    for (int j = 0; j < 512; j += 4) {
        float4 hv4 = *(const float4*)(s_hi + j);
        dv = fmaf(hv4.x, Wo[j * 128 + c],       dv);
        dv = fmaf(hv4.y, Wo[(j + 1) * 128 + c], dv);
        dv = fmaf(hv4.z, Wo[(j + 2) * 128 + c], dv);
        dv = fmaf(hv4.w, Wo[(j + 3) * 128 + c], dv);
    }
    float x2 = h1 + dv;

    // ---- LN2 ----
    __syncthreads();   // protect s_red reuse
    s = x2; q = x2 * x2;
    #pragma unroll
    for (int o = 16; o; o >>= 1) {
        s += __shfl_xor_sync(0xffffffffu, s, o);
        q += __shfl_xor_sync(0xffffffffu, q, o);
    }
    if ((c & 31) == 0) { s_red[c >> 5] = s; s_red[8 + (c >> 5)] = q; }
    __syncthreads();
    s = s_red[0] + s_red[1] + s_red[2] + s_red[3];
    q = s_red[8] + s_red[9] + s_red[10] + s_red[11];
    float mean2 = s * (1.0f / (float)Hv);
    float var2  = q * (1.0f / (float)Hv) - mean2 * mean2;
    float h2 = (x2 - mean2) * rsqrtf(var2 + 1e-5f) * g2[c] + be2[c];

    out[(size_t)bl * Hv + c] = maskV[bl] * h2;
}

// ---------------------------------------------------------------------------

extern "C" void kernel_launch(void* const* d_in, const int* in_sizes, int n_in,
                              void* d_out, int out_size) {
    const float* hV    = (const float*)d_in[0];
    const float* hE    = (const float*)d_in[1];
    // d_in[2] = E_idx (unused by the reference forward)
    const float* Xn    = (const float*)d_in[3];
    const float* maskV = (const float*)d_in[4];
    const float* maskA = (const float*)d_in[5];
    const float* Wp    = (const float*)d_in[6];
    const float* bp    = (const float*)d_in[7];
    const float* W1    = (const float*)d_in[8];
    const float* b1    = (const float*)d_in[9];
    const float* W2    = (const float*)d_in[10];
    const float* b2    = (const float*)d_in[11];
    const float* W3    = (const float*)d_in[12];
    const float* b3    = (const float*)d_in[13];
    const float* Wi    = (const float*)d_in[14];
    const float* bi    = (const float*)d_in[15];
    const float* Wo    = (const float*)d_in[16];
    const float* bo    = (const float*)d_in[17];
    const float* g1    = (const float*)d_in[18];
    const float* be1   = (const float*)d_in[19];
    const float* g2    = (const float*)d_in[20];
    const float* be2   = (const float*)d_in[21];
    float* out = (float*)d_out;

    const int smem_bytes = 18304 * 4;  // 73,216 B dynamic smem for main_kernel
    cudaFuncSetAttribute(main_kernel, cudaFuncAttributeMaxDynamicSharedMemorySize,
                         smem_bytes);

    geo_kernel<<<Bv * Lv, 128>>>(hE, Xn, Wp, bp);
    main_kernel<<<Bv * Lv, 128, smem_bytes>>>(hV, hE, maskV, maskA,
                                              W1, b1, W2, b2, W3, b3,
                                              Wi, bi, Wo, bo,
                                              g1, be1, g2, be2, out);
}

// round 2
// speedup vs baseline: 1.8553x; 1.8553x over previous
#include <cuda_runtime.h>
#include <cuda_bf16.h>
#include <math.h>

#define Bv 8
#define Lv 512
#define Kv 30
#define Hv 128
#define NINv 384
#define FEATv 72
#define EPSv 1e-8f

#define NSITE (Bv * Lv)          // 4096
#define MROWS (NSITE * Kv)       // 122880
#define KA 480                   // padded A width: 384 hE + 72 feats + 24 zero
#define FCOL 384                 // feature columns start

// ------------------------- global scratch (static, no allocs) -------------
__device__ __nv_bfloat16 g_Ah[(size_t)MROWS * KA];
__device__ __nv_bfloat16 g_Al[(size_t)MROWS * KA];
__device__ __nv_bfloat16 g_C1h[(size_t)MROWS * Hv];
__device__ __nv_bfloat16 g_C1l[(size_t)MROWS * Hv];
__device__ __nv_bfloat16 g_C2h[(size_t)MROWS * Hv];
__device__ __nv_bfloat16 g_C2l[(size_t)MROWS * Hv];
__device__ float g_C3[(size_t)MROWS * Hv];
__device__ float g_bias1[(size_t)NSITE * Hv];
__device__ __nv_bfloat16 g_W1h[KA * Hv], g_W1l[KA * Hv];
__device__ __nv_bfloat16 g_W2h[Hv * Hv], g_W2l[Hv * Hv];
__device__ __nv_bfloat16 g_W3h[Hv * Hv], g_W3l[Hv * Hv];

__device__ __forceinline__ float geluf(float x) {
    return 0.5f * x * (1.0f + erff(x * 0.7071067811865476f));
}

__device__ __forceinline__ void bsplit(float x, __nv_bfloat16& h, __nv_bfloat16& l) {
    h = __float2bfloat16(x);
    l = __float2bfloat16(x - __bfloat162float(h));
}

// ------------------------- small prep kernels -----------------------------
__global__ void wprep_kernel(const float* __restrict__ W1,
                             const float* __restrict__ W2,
                             const float* __restrict__ W3) {
    int idx = blockIdx.x * 256 + threadIdx.x;
    if (idx < KA * Hv) {
        int j = idx / Hv, c = idx % Hv;
        float v = (j < 456) ? W1[(Hv + j) * Hv + c] : 0.0f;
        bsplit(v, g_W1h[idx], g_W1l[idx]);
    } else if (idx < KA * Hv + Hv * Hv) {
        int i2 = idx - KA * Hv;
        bsplit(W2[i2], g_W2h[i2], g_W2l[i2]);
    } else if (idx < KA * Hv + 2 * Hv * Hv) {
        int i3 = idx - KA * Hv - Hv * Hv;
        bsplit(W3[i3], g_W3h[i3], g_W3l[i3]);
    }
}

// node-term bias: bias1[site][c] = b1[c] + sum_r hV[site,r] * W1[r,c]  (exact fp32)
__global__ __launch_bounds__(128) void bias1_kernel(const float* __restrict__ hV,
                                                    const float* __restrict__ W1,
                                                    const float* __restrict__ b1) {
    extern __shared__ float bsm[];          // 16384 W1 tile + 128 hv
    float* sW = bsm;
    float* shv = bsm + 16384;
    int c = threadIdx.x;
    for (int i = c; i < 16384; i += 128) sW[i] = W1[i];
    __syncthreads();
    for (int site = blockIdx.x; site < NSITE; site += gridDim.x) {
        shv[c] = hV[(size_t)site * Hv + c];
        __syncthreads();
        float acc = b1[c];
        #pragma unroll 8
        for (int r = 0; r < Hv; r++) acc = fmaf(shv[r], sW[r * Hv + c], acc);
        g_bias1[(size_t)site * Hv + c] = acc;
        __syncthreads();
    }
}

// Build frame: R columns = [e0 e1 e2]; R[i*3+j] = e_j[i]; t = CA
__device__ __forceinline__ void make_frame(const float* __restrict__ x,
                                           float* __restrict__ R,
                                           float* __restrict__ t) {
    float Nx = x[0], Ny = x[1], Nz = x[2];
    float CAx = x[3], CAy = x[4], CAz = x[5];
    float Cx = x[6], Cy = x[7], Cz = x[8];
    float e0x = CAx - Nx, e0y = CAy - Ny, e0z = CAz - Nz;
    float inv = 1.0f / sqrtf(e0x * e0x + e0y * e0y + e0z * e0z + EPSv);
    e0x *= inv; e0y *= inv; e0z *= inv;
    float e1x = Cx - CAx, e1y = Cy - CAy, e1z = Cz - CAz;
    float d = e0x * e1x + e0y * e1y + e0z * e1z;
    e1x -= e0x * d; e1y -= e0y * d; e1z -= e0z * d;
    inv = 1.0f / sqrtf(e1x * e1x + e1y * e1y + e1z * e1z + EPSv);
    e1x *= inv; e1y *= inv; e1z *= inv;
    float e2x = e0y * e1z - e0z * e1y;
    float e2y = e0z * e1x - e0x * e1z;
    float e2z = e0x * e1y - e0y * e1x;
    R[0] = e0x; R[1] = e1x; R[2] = e2x;
    R[3] = e0y; R[4] = e1y; R[5] = e2y;
    R[6] = e0z; R[7] = e1z; R[8] = e2z;
    t[0] = CAx; t[1] = CAy; t[2] = CAz;
}

// ---------------------------------------------------------------------------
// geoA: geometry features + build split-bf16 A matrix rows for this site
// A cols: [0..383]=h_E, [384..455]=feats (ple24,pln8,npl24,npln8,npgn8), [456..479]=0
// ---------------------------------------------------------------------------
__global__ void __launch_bounds__(128) geoA_kernel(
    const float* __restrict__ hE,
    const float* __restrict__ Xn,
    const float* __restrict__ Wp,
    const float* __restrict__ bp)
{
    int bl = blockIdx.x;
    int tid = threadIdx.x;
    int w = tid >> 5, lane = tid & 31;

    __shared__ float s_hvp0[128];
    __shared__ float s_hvp[4][128];
    __shared__ float s_R[4][9], s_t[4][3], s_pl[4][24], s_npg[4][24];
    __shared__ float s_R0[9], s_t0[3], s_plocal[24], s_plnv[8], s_pglob[24];
    __shared__ float s_feat[Kv][FEATv];

    // ---- phase 0: k = 0 reference quantities ----
    const float* hE0 = hE + ((size_t)bl * Kv) * NINv;
    s_hvp0[tid] = hE0[256 + tid];
    if (tid == 0) make_frame(Xn + ((size_t)bl * Kv) * 9, s_R0, s_t0);
    __syncthreads();
    if (tid < 24) {
        float acc = bp[tid];
        #pragma unroll 4
        for (int i = 0; i < 128; i++) acc += s_hvp0[i] * Wp[i * 24 + tid];
        s_plocal[tid] = acc;
    }
    __syncthreads();
    if (tid < 8) {
        float a = s_plocal[tid * 3], b = s_plocal[tid * 3 + 1], cc = s_plocal[tid * 3 + 2];
        s_plnv[tid] = sqrtf(a * a + b * b + cc * cc + EPSv);
    }
    if (tid < 24) {
        int n = tid / 3, i = tid % 3;
        float v = s_t0[i];
        #pragma unroll
        for (int j = 0; j < 3; j++) v += s_R0[i * 3 + j] * s_plocal[n * 3 + j];
        s_pglob[tid] = v;
    }
    __syncthreads();

    // ---- phase 1: per-edge features -> s_feat ----
    for (int k = w; k < Kv; k += 4) {
        const float* hEk = hE + ((size_t)bl * Kv + k) * NINv;
        for (int i = lane; i < 128; i += 32) s_hvp[w][i] = hEk[256 + i];
        if (lane == 0) make_frame(Xn + ((size_t)bl * Kv + k) * 9, s_R[w], s_t[w]);
        __syncwarp();
        if (lane < 24) {
            float acc = bp[lane];
            #pragma unroll 4
            for (int i = 0; i < 128; i++) acc += s_hvp[w][i] * Wp[i * 24 + lane];
            s_pl[w][lane] = acc;
        }
        __syncwarp();
        if (lane < 24) {
            int n = lane / 3, i = lane % 3;
            float v = s_t[w][i];
            #pragma unroll
            for (int j = 0; j < 3; j++) v += s_R[w][i * 3 + j] * s_pl[w][n * 3 + j];
            s_npg[w][lane] = v;
        }
        __syncwarp();
        if (lane < 24) s_feat[k][lane] = s_plocal[lane];
        if (lane < 8)  s_feat[k][24 + lane] = s_plnv[lane];
        if (lane < 24) {
            int n = lane / 3, i = lane % 3;
            float v = 0.0f;
            #pragma unroll
            for (int j = 0; j < 3; j++)
                v += s_R0[j * 3 + i] * (s_npg[w][n * 3 + j] - s_t0[j]);
            s_feat[k][32 + lane] = v;
            s_pl[w][lane] = v;
        }
        __syncwarp();
        if (lane < 8) {
            float a = s_pl[w][lane * 3], b = s_pl[w][lane * 3 + 1], cc = s_pl[w][lane * 3 + 2];
            s_feat[k][56 + lane] = sqrtf(a * a + b * b + cc * cc + EPSv);
            float dx = s_pglob[lane * 3]     - s_npg[w][lane * 3];
            float dy = s_pglob[lane * 3 + 1] - s_npg[w][lane * 3 + 1];
            float dz = s_pglob[lane * 3 + 2] - s_npg[w][lane * 3 + 2];
            s_feat[k][64 + lane] = sqrtf(dx * dx + dy * dy + dz * dz + EPSv);
        }
        __syncwarp();
    }
    __syncthreads();

    // ---- write A rows (split bf16) ----
    size_t base_row = (size_t)bl * Kv;
    const float* src = hE + (size_t)bl * Kv * NINv;
    for (int idx = tid; idx < Kv * NINv; idx += 128) {
        int k = idx / NINv, j = idx - k * NINv;
        size_t o = (base_row + k) * KA + j;
        bsplit(src[idx], g_Ah[o], g_Al[o]);
    }
    for (int idx = tid; idx < Kv * FEATv; idx += 128) {
        int k = idx / FEATv, f = idx - k * FEATv;
        size_t o = (base_row + k) * KA + FCOL + f;
        bsplit(s_feat[k][f], g_Ah[o], g_Al[o]);
    }
    for (int idx = tid; idx < Kv * (KA - 456); idx += 128) {
        int k = idx / (KA - 456), f = idx - k * (KA - 456);
        size_t o = (base_row + k) * KA + 456 + f;
        g_Ah[o] = __float2bfloat16(0.0f);
        g_Al[o] = __float2bfloat16(0.0f);
    }
}

// ---------------------------------------------------------------------------
// Split-bf16 tensor-core GEMM: C[M x 128] = (Ah+Al) @ (Bh+Bl) + bias
// MODE 1: bias per-site (row/30), gelu, split-bf16 out
// MODE 2: bias per-col, gelu, split-bf16 out
// MODE 3: bias per-col, raw fp32 out
// Block: 256 thr (8 warps, 4x2), tile 128(M) x 128(N), k-chunks of 32, 2-stage cp.async
// ---------------------------------------------------------------------------
#define OFF_AH 0
#define OFF_AL 10240
#define OFF_BH 20480
#define OFF_BL 29184
#define STAGE_BYTES 37888

__device__ __forceinline__ void cpasync16(unsigned dst, const void* src) {
    asm volatile("cp.async.cg.shared.global [%0], [%1], 16;\n" :: "r"(dst), "l"(src));
}
__device__ __forceinline__ void ldm_x4(unsigned* r, unsigned addr) {
    asm volatile("ldmatrix.sync.aligned.m8n8.x4.shared.b16 {%0,%1,%2,%3}, [%4];"
        : "=r"(r[0]), "=r"(r[1]), "=r"(r[2]), "=r"(r[3]) : "r"(addr));
}
__device__ __forceinline__ void ldm_x4_t(unsigned* r, unsigned addr) {
    asm volatile("ldmatrix.sync.aligned.m8n8.x4.trans.shared.b16 {%0,%1,%2,%3}, [%4];"
        : "=r"(r[0]), "=r"(r[1]), "=r"(r[2]), "=r"(r[3]) : "r"(addr));
}
__device__ __forceinline__ void mma_bf16(float* d, const unsigned* a, unsigned b0, unsigned b1) {
    asm volatile("mma.sync.aligned.m16n8k16.row.col.f32.bf16.bf16.f32 "
        "{%0,%1,%2,%3}, {%4,%5,%6,%7}, {%8,%9}, {%0,%1,%2,%3};"
        : "+f"(d[0]), "+f"(d[1]), "+f"(d[2]), "+f"(d[3])
        : "r"(a[0]), "r"(a[1]), "r"(a[2]), "r"(a[3]), "r"(b0), "r"(b1));
}

__device__ __forceinline__ void gemm_load_chunk(
    unsigned sb, const __nv_bfloat16* __restrict__ Ah, const __nv_bfloat16* __restrict__ Al,
    const __nv_bfloat16* __restrict__ Bh, const __nv_bfloat16* __restrict__ Bl,
    int K, int rowBase, int kc, int tid)
{
    #pragma unroll
    for (int i = 0; i < 2; i++) {
        int tt = tid + i * 256;
        int row = tt >> 2, seg = tt & 3;
        const __nv_bfloat16* ga = Ah + (size_t)(rowBase + row) * K + kc + seg * 8;
        cpasync16(sb + OFF_AH + (row * 40 + seg * 8) * 2, ga);
        ga = Al + (size_t)(rowBase + row) * K + kc + seg * 8;
        cpasync16(sb + OFF_AL + (row * 40 + seg * 8) * 2, ga);
        int rb = tt >> 4, sg = tt & 15;
        const __nv_bfloat16* gb = Bh + (size_t)(kc + rb) * Hv + sg * 8;
        cpasync16(sb + OFF_BH + (rb * 136 + sg * 8) * 2, gb);
        gb = Bl + (size_t)(kc + rb) * Hv + sg * 8;
        cpasync16(sb + OFF_BL + (rb * 136 + sg * 8) * 2, gb);
    }
    asm volatile("cp.async.commit_group;\n" ::);
}

template <int MODE>
__global__ __launch_bounds__(256, 2) void gemm_kernel(
    const __nv_bfloat16* __restrict__ Ah, const __nv_bfloat16* __restrict__ Al,
    const __nv_bfloat16* __restrict__ Bh, const __nv_bfloat16* __restrict__ Bl,
    int K,
    const float* __restrict__ bias,
    __nv_bfloat16* __restrict__ Oh, __nv_bfloat16* __restrict__ Ol,
    float* __restrict__ Of)
{
    extern __shared__ __align__(16) unsigned char gsm[];
    unsigned sbase = (unsigned)__cvta_generic_to_shared(gsm);

    int tid = threadIdx.x;
    int lane = tid & 31, w = tid >> 5;
    int wm = w >> 1, wn = w & 1;
    int rowBase = blockIdx.x * 128;

    float acc[2][8][4];
    #pragma unroll
    for (int i = 0; i < 2; i++)
        #pragma unroll
        for (int j = 0; j < 8; j++)
            #pragma unroll
            for (int q = 0; q < 4; q++) acc[i][j][q] = 0.0f;

    int nch = K >> 5;
    gemm_load_chunk(sbase, Ah, Al, Bh, Bl, K, rowBase, 0, tid);

    for (int c = 0; c < nch; c++) {
        if (c + 1 < nch) {
            gemm_load_chunk(sbase + ((c + 1) & 1) * STAGE_BYTES, Ah, Al, Bh, Bl,
                            K, rowBase, (c + 1) * 32, tid);
            asm volatile("cp.async.wait_group 1;\n" ::);
        } else {
            asm volatile("cp.async.wait_group 0;\n" ::);
        }
        __syncthreads();

        unsigned sb = sbase + (c & 1) * STAGE_BYTES;
        #pragma unroll
        for (int kk = 0; kk < 32; kk += 16) {
            unsigned aH[2][4], aL[2][4];
            #pragma unroll
            for (int ma = 0; ma < 2; ma++) {
                int row = wm * 32 + ma * 16 + (lane & 15);
                unsigned off = (unsigned)((row * 40 + kk + ((lane >> 4) << 3)) * 2);
                ldm_x4(aH[ma], sb + OFF_AH + off);
                ldm_x4(aL[ma], sb + OFF_AL + off);
            }
            #pragma unroll
            for (int nb = 0; nb < 4; nb++) {
                int col = wn * 64 + nb * 16;
                unsigned offb = (unsigned)(((kk + (lane & 15)) * 136 + col + ((lane >> 4) << 3)) * 2);
                unsigned bh[4], bl[4];
                ldm_x4_t(bh, sb + OFF_BH + offb);
                ldm_x4_t(bl, sb + OFF_BL + offb);
                #pragma unroll
                for (int ma = 0; ma < 2; ma++) {
                    mma_bf16(acc[ma][2 * nb],     aH[ma], bh[0], bh[1]);
                    mma_bf16(acc[ma][2 * nb],     aH[ma], bl[0], bl[1]);
                    mma_bf16(acc[ma][2 * nb],     aL[ma], bh[0], bh[1]);
                    mma_bf16(acc[ma][2 * nb + 1], aH[ma], bh[2], bh[3]);
                    mma_bf16(acc[ma][2 * nb + 1], aH[ma], bl[2], bl[3]);
                    mma_bf16(acc[ma][2 * nb + 1], aL[ma], bh[2], bh[3]);
                }
            }
        }
        __syncthreads();
    }

    // epilogue
    #pragma unroll
    for (int ma = 0; ma < 2; ma++) {
        #pragma unroll
        for (int na = 0; na < 8; na++) {
            int r0 = wm * 32 + ma * 16 + (lane >> 2);
            int c0 = wn * 64 + na * 8 + ((lane & 3) << 1);
            #pragma unroll
            for (int h = 0; h < 2; h++) {
                int r = r0 + h * 8;
                size_t grow = (size_t)(rowBase + r);
                float b0, b1;
                if (MODE == 1) {
                    int site = (rowBase + r) / Kv;
                    b0 = bias[(size_t)site * Hv + c0];
                    b1 = bias[(size_t)site * Hv + c0 + 1];
                } else {
                    b0 = bias[c0];
                    b1 = bias[c0 + 1];
                }
                float x0 = acc[ma][na][2 * h] + b0;
                float x1 = acc[ma][na][2 * h + 1] + b1;
                if (MODE == 3) {
                    float2 v; v.x = x0; v.y = x1;
                    *(float2*)(Of + grow * Hv + c0) = v;
                } else {
                    float y0 = geluf(x0), y1 = geluf(x1);
                    __nv_bfloat16 h0 = __float2bfloat16(y0);
                    __nv_bfloat16 h1 = __float2bfloat16(y1);
                    __nv_bfloat162 hh; hh.x = h0; hh.y = h1;
                    *(__nv_bfloat162*)(Oh + grow * Hv + c0) = hh;
                    __nv_bfloat162 ll;
                    ll.x = __float2bfloat16(y0 - __bfloat162float(h0));
                    ll.y = __float2bfloat16(y1 - __bfloat162float(h1));
                    *(__nv_bfloat162*)(Ol + grow * Hv + c0) = ll;
                }
            }
        }
    }
}

// ---------------------------------------------------------------------------
// Final: masked mean over k + LN1 + FFN + LN2 + masked out. 16 sites/block.
// ---------------------------------------------------------------------------
#define SPB 16
__global__ __launch_bounds__(128) void final_kernel(
    const float* __restrict__ hV, const float* __restrict__ maskV,
    const float* __restrict__ maskA,
    const float* __restrict__ Wi, const float* __restrict__ bi,
    const float* __restrict__ Wo, const float* __restrict__ bo,
    const float* __restrict__ g1, const float* __restrict__ be1,
    const float* __restrict__ g2, const float* __restrict__ be2,
    float* __restrict__ out)
{
    __shared__ float s_h[SPB][Hv];
    __shared__ float s_f[SPB][4 * Hv];
    __shared__ float s_red[8];
    int c = threadIdx.x;
    int base_site = blockIdx.x * SPB;

    for (int s = 0; s < SPB; s++) {
        int site = base_site + s;
        const float* c3 = g_C3 + (size_t)site * Kv * Hv + c;
        const float* ma = maskA + (size_t)site * Kv;
        float nm = 0.0f;
        #pragma unroll
        for (int k = 0; k < Kv; k++) nm += c3[k * Hv] * ma[k];
        nm *= (1.0f / (float)Kv);
        float xv = hV[(size_t)site * Hv + c] + nm;
        float sum = xv, sq = xv * xv;
        #pragma unroll
        for (int o = 16; o; o >>= 1) {
            sum += __shfl_xor_sync(0xffffffffu, sum, o);
            sq  += __shfl_xor_sync(0xffffffffu, sq, o);
        }
        if ((c & 31) == 0) { s_red[c >> 5] = sum; s_red[4 + (c >> 5)] = sq; }
        __syncthreads();
        sum = s_red[0] + s_red[1] + s_red[2] + s_red[3];
        sq  = s_red[4] + s_red[5] + s_red[6] + s_red[7];
        float mean = sum * (1.0f / Hv);
        float var  = sq * (1.0f / Hv) - mean * mean;
        s_h[s][c] = (xv - mean) * rsqrtf(var + 1e-5f) * g1[c] + be1[c];
        __syncthreads();
    }

    // FFN layer 1
    float hi[SPB][4];
    #pragma unroll
    for (int s = 0; s < SPB; s++) {
        hi[s][0] = bi[c];        hi[s][1] = bi[c + 128];
        hi[s][2] = bi[c + 256];  hi[s][3] = bi[c + 384];
    }
    for (int r = 0; r < Hv; r++) {
        const float* wr = Wi + (size_t)r * 512;
        float w0 = wr[c], w1 = wr[c + 128], w2 = wr[c + 256], w3 = wr[c + 384];
        #pragma unroll
        for (int s = 0; s < SPB; s++) {
            float hv = s_h[s][r];
            hi[s][0] = fmaf(hv, w0, hi[s][0]);
            hi[s][1] = fmaf(hv, w1, hi[s][1]);
            hi[s][2] = fmaf(hv, w2, hi[s][2]);
            hi[s][3] = fmaf(hv, w3, hi[s][3]);
        }
    }
    #pragma unroll
    for (int s = 0; s < SPB; s++) {
        s_f[s][c]       = geluf(hi[s][0]);
        s_f[s][c + 128] = geluf(hi[s][1]);
        s_f[s][c + 256] = geluf(hi[s][2]);
        s_f[s][c + 384] = geluf(hi[s][3]);
    }
    __syncthreads();

    // FFN layer 2
    float d[SPB];
    #pragma unroll
    for (int s = 0; s < SPB; s++) d[s] = bo[c];
    for (int j = 0; j < 512; j++) {
        float w = Wo[(size_t)j * Hv + c];
        #pragma unroll
        for (int s = 0; s < SPB; s++) d[s] = fmaf(s_f[s][j], w, d[s]);
    }

    // LN2 + output
    for (int s = 0; s < SPB; s++) {
        int site = base_site + s;
        float x2 = s_h[s][c] + d[s];
        float sum = x2, sq = x2 * x2;
        #pragma unroll
        for (int o = 16; o; o >>= 1) {
            sum += __shfl_xor_sync(0xffffffffu, sum, o);
            sq  += __shfl_xor_sync(0xffffffffu, sq, o);
        }
        if ((c & 31) == 0) { s_red[c >> 5] = sum; s_red[4 + (c >> 5)] = sq; }
        __syncthreads();
        sum = s_red[0] + s_red[1] + s_red[2] + s_red[3];
        sq  = s_red[4] + s_red[5] + s_red[6] + s_red[7];
        float mean = sum * (1.0f / Hv);
        float var  = sq * (1.0f / Hv) - mean * mean;
        float h2 = (x2 - mean) * rsqrtf(var + 1e-5f) * g2[c] + be2[c];
        out[(size_t)site * Hv + c] = maskV[site] * h2;
        __syncthreads();
    }
}

// ---------------------------------------------------------------------------

extern "C" void kernel_launch(void* const* d_in, const int* in_sizes, int n_in,
                              void* d_out, int out_size) {
    const float* hV    = (const float*)d_in[0];
    const float* hE    = (const float*)d_in[1];
    const float* Xn    = (const float*)d_in[3];
    const float* maskV = (const float*)d_in[4];
    const float* maskA = (const float*)d_in[5];
    const float* Wp    = (const float*)d_in[6];
    const float* bp    = (const float*)d_in[7];
    const float* W1    = (const float*)d_in[8];
    const float* b1    = (const float*)d_in[9];
    const float* W2    = (const float*)d_in[10];
    const float* b2    = (const float*)d_in[11];
    const float* W3    = (const float*)d_in[12];
    const float* b3    = (const float*)d_in[13];
    const float* Wi    = (const float*)d_in[14];
    const float* bi    = (const float*)d_in[15];
    const float* Wo    = (const float*)d_in[16];
    const float* bo    = (const float*)d_in[17];
    const float* g1    = (const float*)d_in[18];
    const float* be1   = (const float*)d_in[19];
    const float* g2    = (const float*)d_in[20];
    const float* be2   = (const float*)d_in[21];
    float* out = (float*)d_out;

    const int gemm_smem = 2 * STAGE_BYTES;   // 75776
    cudaFuncSetAttribute(gemm_kernel<1>, cudaFuncAttributeMaxDynamicSharedMemorySize, gemm_smem);
    cudaFuncSetAttribute(gemm_kernel<2>, cudaFuncAttributeMaxDynamicSharedMemorySize, gemm_smem);
    cudaFuncSetAttribute(gemm_kernel<3>, cudaFuncAttributeMaxDynamicSharedMemorySize, gemm_smem);
    cudaFuncSetAttribute(bias1_kernel, cudaFuncAttributeMaxDynamicSharedMemorySize, 66048);

    // device-symbol addresses (host-side address-of on __device__ vars works via
    // cudaGetSymbolAddress; but passing raw &symbol is invalid — fetch them)
    static void *pAh = nullptr, *pAl, *pC1h, *pC1l, *pC2h, *pC2l, *pC3, *pB1;
    static void *pW1h, *pW1l, *pW2h, *pW2l, *pW3h, *pW3l;
    if (!pAh) {
        cudaGetSymbolAddress(&pAh, g_Ah);   cudaGetSymbolAddress(&pAl, g_Al);
        cudaGetSymbolAddress(&pC1h, g_C1h); cudaGetSymbolAddress(&pC1l, g_C1l);
        cudaGetSymbolAddress(&pC2h, g_C2h); cudaGetSymbolAddress(&pC2l, g_C2l);
        cudaGetSymbolAddress(&pC3, g_C3);   cudaGetSymbolAddress(&pB1, g_bias1);
        cudaGetSymbolAddress(&pW1h, g_W1h); cudaGetSymbolAddress(&pW1l, g_W1l);
        cudaGetSymbolAddress(&pW2h, g_W2h); cudaGetSymbolAddress(&pW2l, g_W2l);
        cudaGetSymbolAddress(&pW3h, g_W3h); cudaGetSymbolAddress(&pW3l, g_W3l);
    }

    wprep_kernel<<<(KA * Hv + 2 * Hv * Hv + 255) / 256, 256>>>(W1, W2, W3);
    bias1_kernel<<<128, 128, 66048>>>(hV, W1, b1);
    geoA_kernel<<<NSITE, 128>>>(hE, Xn, Wp, bp);

    gemm_kernel<1><<<MROWS / 128, 256, gemm_smem>>>(
        (const __nv_bfloat16*)pAh, (const __nv_bfloat16*)pAl,
        (const __nv_bfloat16*)pW1h, (const __nv_bfloat16*)pW1l,
        KA, (const float*)pB1,
        (__nv_bfloat16*)pC1h, (__nv_bfloat16*)pC1l, nullptr);

    gemm_kernel<2><<<MROWS / 128, 256, gemm_smem>>>(
        (const __nv_bfloat16*)pC1h, (const __nv_bfloat16*)pC1l,
        (const __nv_bfloat16*)pW2h, (const __nv_bfloat16*)pW2l,
        Hv, b2,
        (__nv_bfloat16*)pC2h, (__nv_bfloat16*)pC2l, nullptr);

    gemm_kernel<3><<<MROWS / 128, 256, gemm_smem>>>(
        (const __nv_bfloat16*)pC2h, (const __nv_bfloat16*)pC2l,
        (const __nv_bfloat16*)pW3h, (const __nv_bfloat16*)pW3l,
        Hv, b3,
        nullptr, nullptr, (float*)pC3);

    final_kernel<<<NSITE / SPB, 128>>>(hV, maskV, maskA, Wi, bi, Wo, bo,
                                       g1, be1, g2, be2, out);
}

// round 4
// speedup vs baseline: 1.9599x; 1.0564x over previous
#include <cuda_runtime.h>
#include <cuda_bf16.h>
#include <math.h>

#define Bv 8
#define Lv 512
#define Kv 30
#define Hv 128
#define NINv 384
#define FEATv 72
#define EPSv 1e-8f

#define NSITE (Bv * Lv)          // 4096
#define MROWS (NSITE * Kv)       // 122880
#define KA 480                   // padded A width: 384 hE + 72 feats + 24 zero
#define FCOL 384

// ------------------------- global scratch (static, no allocs) -------------
__device__ __nv_bfloat16 g_Ah[(size_t)MROWS * KA];
__device__ __nv_bfloat16 g_Al[(size_t)MROWS * KA];
__device__ float g_C3[(size_t)MROWS * Hv];
__device__ float g_bias1[(size_t)NSITE * Hv];
__device__ __nv_bfloat16 g_W1h[KA * Hv], g_W1l[KA * Hv];
__device__ __nv_bfloat16 g_W2h[Hv * Hv], g_W2l[Hv * Hv];
__device__ __nv_bfloat16 g_W3h[Hv * Hv], g_W3l[Hv * Hv];

__device__ __forceinline__ float geluf(float x) {
    return 0.5f * x * (1.0f + erff(x * 0.7071067811865476f));
}
__device__ __forceinline__ void bsplit(float x, __nv_bfloat16& h, __nv_bfloat16& l) {
    h = __float2bfloat16(x);
    l = __float2bfloat16(x - __bfloat162float(h));
}
__device__ __forceinline__ unsigned packsplit_h(float a, float b) {
    __nv_bfloat162 v; v.x = __float2bfloat16(a); v.y = __float2bfloat16(b);
    return *(unsigned*)&v;
}
__device__ __forceinline__ unsigned packsplit_l(float a, float b) {
    __nv_bfloat16 ha = __float2bfloat16(a), hb = __float2bfloat16(b);
    __nv_bfloat162 v;
    v.x = __float2bfloat16(a - __bfloat162float(ha));
    v.y = __float2bfloat16(b - __bfloat162float(hb));
    return *(unsigned*)&v;
}

// ------------------------- small prep kernels -----------------------------
__global__ void wprep_kernel(const float* __restrict__ W1,
                             const float* __restrict__ W2,
                             const float* __restrict__ W3) {
    int idx = blockIdx.x * 256 + threadIdx.x;
    if (idx < KA * Hv) {
        int j = idx / Hv, c = idx % Hv;
        float v = (j < 456) ? W1[(Hv + j) * Hv + c] : 0.0f;
        bsplit(v, g_W1h[idx], g_W1l[idx]);
    } else if (idx < KA * Hv + Hv * Hv) {
        int i2 = idx - KA * Hv;
        bsplit(W2[i2], g_W2h[i2], g_W2l[i2]);
    } else if (idx < KA * Hv + 2 * Hv * Hv) {
        int i3 = idx - KA * Hv - Hv * Hv;
        bsplit(W3[i3], g_W3h[i3], g_W3l[i3]);
    }
}

// node-term bias: bias1[site][c] = b1[c] + sum_r hV[site,r] * W1[r,c]  (exact fp32)
__global__ __launch_bounds__(128) void bias1_kernel(const float* __restrict__ hV,
                                                    const float* __restrict__ W1,
                                                    const float* __restrict__ b1) {
    extern __shared__ float bsm[];
    float* sW = bsm;
    float* shv = bsm + 16384;
    int c = threadIdx.x;
    for (int i = c; i < 16384; i += 128) sW[i] = W1[i];
    __syncthreads();
    for (int site = blockIdx.x; site < NSITE; site += gridDim.x) {
        shv[c] = hV[(size_t)site * Hv + c];
        __syncthreads();
        float acc = b1[c];
        #pragma unroll 8
        for (int r = 0; r < Hv; r++) acc = fmaf(shv[r], sW[r * Hv + c], acc);
        g_bias1[(size_t)site * Hv + c] = acc;
        __syncthreads();
    }
}

__device__ __forceinline__ void make_frame(const float* __restrict__ x,
                                           float* __restrict__ R,
                                           float* __restrict__ t) {
    float Nx = x[0], Ny = x[1], Nz = x[2];
    float CAx = x[3], CAy = x[4], CAz = x[5];
    float Cx = x[6], Cy = x[7], Cz = x[8];
    float e0x = CAx - Nx, e0y = CAy - Ny, e0z = CAz - Nz;
    float inv = 1.0f / sqrtf(e0x * e0x + e0y * e0y + e0z * e0z + EPSv);
    e0x *= inv; e0y *= inv; e0z *= inv;
    float e1x = Cx - CAx, e1y = Cy - CAy, e1z = Cz - CAz;
    float d = e0x * e1x + e0y * e1y + e0z * e1z;
    e1x -= e0x * d; e1y -= e0y * d; e1z -= e0z * d;
    inv = 1.0f / sqrtf(e1x * e1x + e1y * e1y + e1z * e1z + EPSv);
    e1x *= inv; e1y *= inv; e1z *= inv;
    float e2x = e0y * e1z - e0z * e1y;
    float e2y = e0z * e1x - e0x * e1z;
    float e2z = e0x * e1y - e0y * e1x;
    R[0] = e0x; R[1] = e1x; R[2] = e2x;
    R[3] = e0y; R[4] = e1y; R[5] = e2y;
    R[6] = e0z; R[7] = e1z; R[8] = e2z;
    t[0] = CAx; t[1] = CAy; t[2] = CAz;
}

// ---------------------------------------------------------------------------
// geoA: geometry features + split-bf16 A rows. Wp staged in smem.
// ---------------------------------------------------------------------------
__global__ void __launch_bounds__(128) geoA_kernel(
    const float* __restrict__ hE,
    const float* __restrict__ Xn,
    const float* __restrict__ Wp,
    const float* __restrict__ bp)
{
    int bl = blockIdx.x;
    int tid = threadIdx.x;
    int w = tid >> 5, lane = tid & 31;

    __shared__ float s_Wp[128 * 24];
    __shared__ float s_hvp0[128];
    __shared__ float s_hvp[4][128];
    __shared__ float s_R[4][9], s_t[4][3], s_pl[4][24], s_npg[4][24];
    __shared__ float s_R0[9], s_t0[3], s_plocal[24], s_plnv[8], s_pglob[24];
    __shared__ float s_feat[Kv][FEATv];

    for (int i = tid; i < 128 * 24; i += 128) s_Wp[i] = Wp[i];

    const float* hE0 = hE + ((size_t)bl * Kv) * NINv;
    s_hvp0[tid] = hE0[256 + tid];
    if (tid == 0) make_frame(Xn + ((size_t)bl * Kv) * 9, s_R0, s_t0);
    __syncthreads();
    if (tid < 24) {
        float acc = bp[tid];
        #pragma unroll 8
        for (int i = 0; i < 128; i++) acc += s_hvp0[i] * s_Wp[i * 24 + tid];
        s_plocal[tid] = acc;
    }
    __syncthreads();
    if (tid < 8) {
        float a = s_plocal[tid * 3], b = s_plocal[tid * 3 + 1], cc = s_plocal[tid * 3 + 2];
        s_plnv[tid] = sqrtf(a * a + b * b + cc * cc + EPSv);
    }
    if (tid < 24) {
        int n = tid / 3, i = tid % 3;
        float v = s_t0[i];
        #pragma unroll
        for (int j = 0; j < 3; j++) v += s_R0[i * 3 + j] * s_plocal[n * 3 + j];
        s_pglob[tid] = v;
    }
    __syncthreads();

    for (int k = w; k < Kv; k += 4) {
        const float* hEk = hE + ((size_t)bl * Kv + k) * NINv;
        for (int i = lane; i < 128; i += 32) s_hvp[w][i] = hEk[256 + i];
        if (lane == 0) make_frame(Xn + ((size_t)bl * Kv + k) * 9, s_R[w], s_t[w]);
        __syncwarp();
        if (lane < 24) {
            float acc = bp[lane];
            #pragma unroll 8
            for (int i = 0; i < 128; i++) acc += s_hvp[w][i] * s_Wp[i * 24 + lane];
            s_pl[w][lane] = acc;
        }
        __syncwarp();
        if (lane < 24) {
            int n = lane / 3, i = lane % 3;
            float v = s_t[w][i];
            #pragma unroll
            for (int j = 0; j < 3; j++) v += s_R[w][i * 3 + j] * s_pl[w][n * 3 + j];
            s_npg[w][lane] = v;
        }
        __syncwarp();
        if (lane < 24) s_feat[k][lane] = s_plocal[lane];
        if (lane < 8)  s_feat[k][24 + lane] = s_plnv[lane];
        if (lane < 24) {
            int n = lane / 3, i = lane % 3;
            float v = 0.0f;
            #pragma unroll
            for (int j = 0; j < 3; j++)
                v += s_R0[j * 3 + i] * (s_npg[w][n * 3 + j] - s_t0[j]);
            s_feat[k][32 + lane] = v;
            s_pl[w][lane] = v;
        }
        __syncwarp();
        if (lane < 8) {
            float a = s_pl[w][lane * 3], b = s_pl[w][lane * 3 + 1], cc = s_pl[w][lane * 3 + 2];
            s_feat[k][56 + lane] = sqrtf(a * a + b * b + cc * cc + EPSv);
            float dx = s_pglob[lane * 3]     - s_npg[w][lane * 3];
            float dy = s_pglob[lane * 3 + 1] - s_npg[w][lane * 3 + 1];
            float dz = s_pglob[lane * 3 + 2] - s_npg[w][lane * 3 + 2];
            s_feat[k][64 + lane] = sqrtf(dx * dx + dy * dy + dz * dz + EPSv);
        }
        __syncwarp();
    }
    __syncthreads();

    size_t base_row = (size_t)bl * Kv;
    const float* src = hE + (size_t)bl * Kv * NINv;
    for (int idx = tid; idx < Kv * NINv; idx += 128) {
        int k = idx / NINv, j = idx - k * NINv;
        size_t o = (base_row + k) * KA + j;
        bsplit(src[idx], g_Ah[o], g_Al[o]);
    }
    for (int idx = tid; idx < Kv * FEATv; idx += 128) {
        int k = idx / FEATv, f = idx - k * FEATv;
        size_t o = (base_row + k) * KA + FCOL + f;
        bsplit(s_feat[k][f], g_Ah[o], g_Al[o]);
    }
    for (int idx = tid; idx < Kv * (KA - 456); idx += 128) {
        int k = idx / (KA - 456), f = idx - k * (KA - 456);
        size_t o = (base_row + k) * KA + 456 + f;
        g_Ah[o] = __float2bfloat16(0.0f);
        g_Al[o] = __float2bfloat16(0.0f);
    }
}

// ---------------------------------------------------------------------------
// Fused GEMM: C3 = ( gelu( gelu( A@W1 + bias1 ) @ W2 + b2 ) @ W3 + b3 )
// 3-pass split-bf16 everywhere. Warp owns 16 rows x all 128 N cols, so the
// m16n8 accumulators double as m16k16 A fragments for the next GEMM.
// 8 warps (256 thr), M-tile 128, 3-stage cp.async pipeline for phase 1.
// ---------------------------------------------------------------------------
#define OFF_AH 0
#define OFF_AL 10240
#define OFF_BH 20480
#define OFF_BL 29184
#define STAGE_BYTES 37888
#define OFF_W2H (3 * STAGE_BYTES)              // 113664
#define OFF_W2L (OFF_W2H + 34816)              // 148480
#define OFF_W3H 0
#define OFF_W3L 34816
#define GEMM_SMEM (OFF_W2L + 34816)            // 183296

__device__ __forceinline__ void cpasync16(unsigned dst, const void* src) {
    asm volatile("cp.async.cg.shared.global [%0], [%1], 16;\n" :: "r"(dst), "l"(src));
}
__device__ __forceinline__ void ldm_x4(unsigned* r, unsigned addr) {
    asm volatile("ldmatrix.sync.aligned.m8n8.x4.shared.b16 {%0,%1,%2,%3}, [%4];"
        : "=r"(r[0]), "=r"(r[1]), "=r"(r[2]), "=r"(r[3]) : "r"(addr));
}
__device__ __forceinline__ void ldm_x4_t(unsigned* r, unsigned addr) {
    asm volatile("ldmatrix.sync.aligned.m8n8.x4.trans.shared.b16 {%0,%1,%2,%3}, [%4];"
        : "=r"(r[0]), "=r"(r[1]), "=r"(r[2]), "=r"(r[3]) : "r"(addr));
}
__device__ __forceinline__ void mma_bf16(float* d, const unsigned* a, unsigned b0, unsigned b1) {
    asm volatile("mma.sync.aligned.m16n8k16.row.col.f32.bf16.bf16.f32 "
        "{%0,%1,%2,%3}, {%4,%5,%6,%7}, {%8,%9}, {%0,%1,%2,%3};"
        : "+f"(d[0]), "+f"(d[1]), "+f"(d[2]), "+f"(d[3])
        : "r"(a[0]), "r"(a[1]), "r"(a[2]), "r"(a[3]), "r"(b0), "r"(b1));
}

__device__ __forceinline__ void gemm_load_chunk(
    unsigned sb, const __nv_bfloat16* __restrict__ Ah, const __nv_bfloat16* __restrict__ Al,
    const __nv_bfloat16* __restrict__ Bh, const __nv_bfloat16* __restrict__ Bl,
    int rowBase, int kc, int tid)
{
    #pragma unroll
    for (int i = 0; i < 2; i++) {
        int tt = tid + i * 256;
        int row = tt >> 2, seg = tt & 3;
        const __nv_bfloat16* ga = Ah + (size_t)(rowBase + row) * KA + kc + seg * 8;
        cpasync16(sb + OFF_AH + (row * 40 + seg * 8) * 2, ga);
        ga = Al + (size_t)(rowBase + row) * KA + kc + seg * 8;
        cpasync16(sb + OFF_AL + (row * 40 + seg * 8) * 2, ga);
        int rb = tt >> 4, sg = tt & 15;
        const __nv_bfloat16* gb = Bh + (size_t)(kc + rb) * Hv + sg * 8;
        cpasync16(sb + OFF_BH + (rb * 136 + sg * 8) * 2, gb);
        gb = Bl + (size_t)(kc + rb) * Hv + sg * 8;
        cpasync16(sb + OFF_BL + (rb * 136 + sg * 8) * 2, gb);
    }
    asm volatile("cp.async.commit_group;\n" ::);
}

// Load a 128x128 weight (one split) into smem with row stride 136
__device__ __forceinline__ void load_weight(unsigned sbase, unsigned off,
                                            const __nv_bfloat16* __restrict__ src, int tid) {
    #pragma unroll
    for (int i = 0; i < 8; i++) {
        int idx = tid + i * 256;
        int r = idx >> 4, s = idx & 15;
        cpasync16(sbase + off + (r * 136 + s * 8) * 2, src + r * Hv + s * 8);
    }
}

__global__ __launch_bounds__(256) void fusedgemm_kernel(
    const __nv_bfloat16* __restrict__ Ah, const __nv_bfloat16* __restrict__ Al,
    const __nv_bfloat16* __restrict__ W1h, const __nv_bfloat16* __restrict__ W1l,
    const __nv_bfloat16* __restrict__ W2h, const __nv_bfloat16* __restrict__ W2l,
    const __nv_bfloat16* __restrict__ W3h, const __nv_bfloat16* __restrict__ W3l,
    const float* __restrict__ bias1,
    const float* __restrict__ b2, const float* __restrict__ b3,
    float* __restrict__ C3)
{
    extern __shared__ __align__(16) unsigned char gsm[];
    unsigned sbase = (unsigned)__cvta_generic_to_shared(gsm);

    int tid = threadIdx.x;
    int lane = tid & 31, w = tid >> 5;
    int rowBase = blockIdx.x * 128;

    float acc[16][4];
    #pragma unroll
    for (int t = 0; t < 16; t++)
        #pragma unroll
        for (int q = 0; q < 4; q++) acc[t][q] = 0.0f;

    const int nch = KA / 32;   // 15

    // prologue: W2 splits + chunk0 in group 0; chunk1 in group 1
    load_weight(sbase, OFF_W2H, W2h, tid);
    load_weight(sbase, OFF_W2L, W2l, tid);
    gemm_load_chunk(sbase, Ah, Al, W1h, W1l, rowBase, 0, tid);
    gemm_load_chunk(sbase + STAGE_BYTES, Ah, Al, W1h, W1l, rowBase, 32, tid);

    // -------- phase 1: A @ W1 (K = 480) --------
    for (int c = 0; c < nch; c++) {
        if (c + 2 < nch) {
            gemm_load_chunk(sbase + ((c + 2) % 3) * STAGE_BYTES, Ah, Al, W1h, W1l,
                            rowBase, (c + 2) * 32, tid);
            asm volatile("cp.async.wait_group 2;\n" ::);
        } else if (c + 1 < nch) {
            asm volatile("cp.async.wait_group 1;\n" ::);
        } else {
            asm volatile("cp.async.wait_group 0;\n" ::);
        }
        __syncthreads();

        unsigned sb = sbase + (c % 3) * STAGE_BYTES;
        #pragma unroll
        for (int kk = 0; kk < 32; kk += 16) {
            unsigned aH[4], aL[4];
            {
                int row = w * 16 + (lane & 15);
                unsigned off = (unsigned)((row * 40 + kk + ((lane >> 4) << 3)) * 2);
                ldm_x4(aH, sb + OFF_AH + off);
                ldm_x4(aL, sb + OFF_AL + off);
            }
            #pragma unroll
            for (int nb = 0; nb < 8; nb++) {
                unsigned offb = (unsigned)(((kk + (lane & 15)) * 136 + nb * 16 + ((lane >> 4) << 3)) * 2);
                unsigned bh[4], bl[4];
                ldm_x4_t(bh, sb + OFF_BH + offb);
                ldm_x4_t(bl, sb + OFF_BL + offb);
                mma_bf16(acc[2 * nb],     aH, bh[0], bh[1]);
                mma_bf16(acc[2 * nb],     aH, bl[0], bl[1]);
                mma_bf16(acc[2 * nb],     aL, bh[0], bh[1]);
                mma_bf16(acc[2 * nb + 1], aH, bh[2], bh[3]);
                mma_bf16(acc[2 * nb + 1], aH, bl[2], bl[3]);
                mma_bf16(acc[2 * nb + 1], aL, bh[2], bh[3]);
            }
        }
        __syncthreads();
    }

    // kick off W3 loads into (now free) stage region; overlaps phase-2 compute
    load_weight(sbase, OFF_W3H, W3h, tid);
    load_weight(sbase, OFF_W3L, W3l, tid);
    asm volatile("cp.async.commit_group;\n" ::);

    // phase-1 epilogue: + bias1(site), gelu, split into register A fragments
    int r0 = w * 16 + (lane >> 2);
    int r1 = r0 + 8;
    int site0 = (rowBase + r0) / Kv;
    int site1 = (rowBase + r1) / Kv;
    const float* bs0 = bias1 + (size_t)site0 * Hv;
    const float* bs1 = bias1 + (size_t)site1 * Hv;

    unsigned a_h[16][2], a_l[16][2];
    #pragma unroll
    for (int t = 0; t < 16; t++) {
        int col = t * 8 + ((lane & 3) << 1);
        float2 c0 = *(const float2*)(bs0 + col);
        float2 c1 = *(const float2*)(bs1 + col);
        float v00 = geluf(acc[t][0] + c0.x);
        float v01 = geluf(acc[t][1] + c0.y);
        float v10 = geluf(acc[t][2] + c1.x);
        float v11 = geluf(acc[t][3] + c1.y);
        a_h[t][0] = packsplit_h(v00, v01);
        a_l[t][0] = packsplit_l(v00, v01);
        a_h[t][1] = packsplit_h(v10, v11);
        a_l[t][1] = packsplit_l(v10, v11);
        acc[t][0] = 0.0f; acc[t][1] = 0.0f; acc[t][2] = 0.0f; acc[t][3] = 0.0f;
    }

    // -------- phase 2: C1 @ W2 (K = 128, A from registers) --------
    #pragma unroll
    for (int q = 0; q < 8; q++) {
        unsigned aH[4] = { a_h[2 * q][0], a_h[2 * q][1], a_h[2 * q + 1][0], a_h[2 * q + 1][1] };
        unsigned aL[4] = { a_l[2 * q][0], a_l[2 * q][1], a_l[2 * q + 1][0], a_l[2 * q + 1][1] };
        #pragma unroll
        for (int nb = 0; nb < 8; nb++) {
            unsigned offb = (unsigned)(((q * 16 + (lane & 15)) * 136 + nb * 16 + ((lane >> 4) << 3)) * 2);
            unsigned bh[4], bl[4];
            ldm_x4_t(bh, sbase + OFF_W2H + offb);
            ldm_x4_t(bl, sbase + OFF_W2L + offb);
            mma_bf16(acc[2 * nb],     aH, bh[0], bh[1]);
            mma_bf16(acc[2 * nb],     aH, bl[0], bl[1]);
            mma_bf16(acc[2 * nb],     aL, bh[0], bh[1]);
            mma_bf16(acc[2 * nb + 1], aH, bh[2], bh[3]);
            mma_bf16(acc[2 * nb + 1], aH, bl[2], bl[3]);
            mma_bf16(acc[2 * nb + 1], aL, bh[2], bh[3]);
        }
    }

    // wait for W3 in smem (all threads), then barrier for cross-thread visibility
    asm volatile("cp.async.wait_group 0;\n" ::);
    __syncthreads();

    // phase-2 epilogue: + b2, gelu, split
    #pragma unroll
    for (int t = 0; t < 16; t++) {
        int col = t * 8 + ((lane & 3) << 1);
        float2 bb = *(const float2*)(b2 + col);
        float v00 = geluf(acc[t][0] + bb.x);
        float v01 = geluf(acc[t][1] + bb.y);
        float v10 = geluf(acc[t][2] + bb.x);
        float v11 = geluf(acc[t][3] + bb.y);
        a_h[t][0] = packsplit_h(v00, v01);
        a_l[t][0] = packsplit_l(v00, v01);
        a_h[t][1] = packsplit_h(v10, v11);
        a_l[t][1] = packsplit_l(v10, v11);
        acc[t][0] = 0.0f; acc[t][1] = 0.0f; acc[t][2] = 0.0f; acc[t][3] = 0.0f;
    }

    // -------- phase 3: C2 @ W3 --------
    #pragma unroll
    for (int q = 0; q < 8; q++) {
        unsigned aH[4] = { a_h[2 * q][0], a_h[2 * q][1], a_h[2 * q + 1][0], a_h[2 * q + 1][1] };
        unsigned aL[4] = { a_l[2 * q][0], a_l[2 * q][1], a_l[2 * q + 1][0], a_l[2 * q + 1][1] };
        #pragma unroll
        for (int nb = 0; nb < 8; nb++) {
            unsigned offb = (unsigned)(((q * 16 + (lane & 15)) * 136 + nb * 16 + ((lane >> 4) << 3)) * 2);
            unsigned bh[4], bl[4];
            ldm_x4_t(bh, sbase + OFF_W3H + offb);
            ldm_x4_t(bl, sbase + OFF_W3L + offb);
            mma_bf16(acc[2 * nb],     aH, bh[0], bh[1]);
            mma_bf16(acc[2 * nb],     aH, bl[0], bl[1]);
            mma_bf16(acc[2 * nb],     aL, bh[0], bh[1]);
            mma_bf16(acc[2 * nb + 1], aH, bh[2], bh[3]);
            mma_bf16(acc[2 * nb + 1], aH, bl[2], bl[3]);
            mma_bf16(acc[2 * nb + 1], aL, bh[2], bh[3]);
        }
    }

    // final epilogue: + b3, store raw fp32 C3
    #pragma unroll
    for (int t = 0; t < 16; t++) {
        int col = t * 8 + ((lane & 3) << 1);
        float2 bb = *(const float2*)(b3 + col);
        float2 v0; v0.x = acc[t][0] + bb.x; v0.y = acc[t][1] + bb.y;
        float2 v1; v1.x = acc[t][2] + bb.x; v1.y = acc[t][3] + bb.y;
        *(float2*)(C3 + (size_t)(rowBase + r0) * Hv + col) = v0;
        *(float2*)(C3 + (size_t)(rowBase + r1) * Hv + col) = v1;
    }
}

// ---------------------------------------------------------------------------
// Final: masked mean over k + LN1 + FFN + LN2 + masked out. 16 sites/block.
// ---------------------------------------------------------------------------
#define SPB 16
__global__ __launch_bounds__(128) void final_kernel(
    const float* __restrict__ hV, const float* __restrict__ maskV,
    const float* __restrict__ maskA,
    const float* __restrict__ Wi, const float* __restrict__ bi,
    const float* __restrict__ Wo, const float* __restrict__ bo,
    const float* __restrict__ g1, const float* __restrict__ be1,
    const float* __restrict__ g2, const float* __restrict__ be2,
    float* __restrict__ out)
{
    __shared__ float s_h[SPB][Hv];
    __shared__ float s_f[SPB][4 * Hv];
    __shared__ float s_red[8];
    int c = threadIdx.x;
    int base_site = blockIdx.x * SPB;

    for (int s = 0; s < SPB; s++) {
        int site = base_site + s;
        const float* c3 = g_C3 + (size_t)site * Kv * Hv + c;
        const float* ma = maskA + (size_t)site * Kv;
        float nm = 0.0f;
        #pragma unroll
        for (int k = 0; k < Kv; k++) nm += c3[k * Hv] * ma[k];
        nm *= (1.0f / (float)Kv);
        float xv = hV[(size_t)site * Hv + c] + nm;
        float sum = xv, sq = xv * xv;
        #pragma unroll
        for (int o = 16; o; o >>= 1) {
            sum += __shfl_xor_sync(0xffffffffu, sum, o);
            sq  += __shfl_xor_sync(0xffffffffu, sq, o);
        }
        if ((c & 31) == 0) { s_red[c >> 5] = sum; s_red[4 + (c >> 5)] = sq; }
        __syncthreads();
        sum = s_red[0] + s_red[1] + s_red[2] + s_red[3];
        sq  = s_red[4] + s_red[5] + s_red[6] + s_red[7];
        float mean = sum * (1.0f / Hv);
        float var  = sq * (1.0f / Hv) - mean * mean;
        s_h[s][c] = (xv - mean) * rsqrtf(var + 1e-5f) * g1[c] + be1[c];
        __syncthreads();
    }

    float hi[SPB][4];
    #pragma unroll
    for (int s = 0; s < SPB; s++) {
        hi[s][0] = bi[c];        hi[s][1] = bi[c + 128];
        hi[s][2] = bi[c + 256];  hi[s][3] = bi[c + 384];
    }
    for (int r = 0; r < Hv; r++) {
        const float* wr = Wi + (size_t)r * 512;
        float w0 = wr[c], w1 = wr[c + 128], w2 = wr[c + 256], w3 = wr[c + 384];
        #pragma unroll
        for (int s = 0; s < SPB; s++) {
            float hv = s_h[s][r];
            hi[s][0] = fmaf(hv, w0, hi[s][0]);
            hi[s][1] = fmaf(hv, w1, hi[s][1]);
            hi[s][2] = fmaf(hv, w2, hi[s][2]);
            hi[s][3] = fmaf(hv, w3, hi[s][3]);
        }
    }
    #pragma unroll
    for (int s = 0; s < SPB; s++) {
        s_f[s][c]       = geluf(hi[s][0]);
        s_f[s][c + 128] = geluf(hi[s][1]);
        s_f[s][c + 256] = geluf(hi[s][2]);
        s_f[s][c + 384] = geluf(hi[s][3]);
    }
    __syncthreads();

    float d[SPB];
    #pragma unroll
    for (int s = 0; s < SPB; s++) d[s] = bo[c];
    for (int j = 0; j < 512; j++) {
        float w = Wo[(size_t)j * Hv + c];
        #pragma unroll
        for (int s = 0; s < SPB; s++) d[s] = fmaf(s_f[s][j], w, d[s]);
    }

    for (int s = 0; s < SPB; s++) {
        int site = base_site + s;
        float x2 = s_h[s][c] + d[s];
        float sum = x2, sq = x2 * x2;
        #pragma unroll
        for (int o = 16; o; o >>= 1) {
            sum += __shfl_xor_sync(0xffffffffu, sum, o);
            sq  += __shfl_xor_sync(0xffffffffu, sq, o);
        }
        if ((c & 31) == 0) { s_red[c >> 5] = sum; s_red[4 + (c >> 5)] = sq; }
        __syncthreads();
        sum = s_red[0] + s_red[1] + s_red[2] + s_red[3];
        sq  = s_red[4] + s_red[5] + s_red[6] + s_red[7];
        float mean = sum * (1.0f / Hv);
        float var  = sq * (1.0f / Hv) - mean * mean;
        float h2 = (x2 - mean) * rsqrtf(var + 1e-5f) * g2[c] + be2[c];
        out[(size_t)site * Hv + c] = maskV[site] * h2;
        __syncthreads();
    }
}

// ---------------------------------------------------------------------------

extern "C" void kernel_launch(void* const* d_in, const int* in_sizes, int n_in,
                              void* d_out, int out_size) {
    const float* hV    = (const float*)d_in[0];
    const float* hE    = (const float*)d_in[1];
    const float* Xn    = (const float*)d_in[3];
    const float* maskV = (const float*)d_in[4];
    const float* maskA = (const float*)d_in[5];
    const float* Wp    = (const float*)d_in[6];
    const float* bp    = (const float*)d_in[7];
    const float* W1    = (const float*)d_in[8];
    const float* b1    = (const float*)d_in[9];
    const float* W2    = (const float*)d_in[10];
    const float* b2    = (const float*)d_in[11];
    const float* W3    = (const float*)d_in[12];
    const float* b3    = (const float*)d_in[13];
    const float* Wi    = (const float*)d_in[14];
    const float* bi    = (const float*)d_in[15];
    const float* Wo    = (const float*)d_in[16];
    const float* bo    = (const float*)d_in[17];
    const float* g1    = (const float*)d_in[18];
    const float* be1   = (const float*)d_in[19];
    const float* g2    = (const float*)d_in[20];
    const float* be2   = (const float*)d_in[21];
    float* out = (float*)d_out;

    cudaFuncSetAttribute(fusedgemm_kernel, cudaFuncAttributeMaxDynamicSharedMemorySize, GEMM_SMEM);
    cudaFuncSetAttribute(bias1_kernel, cudaFuncAttributeMaxDynamicSharedMemorySize, 66048);

    static void *pAh = nullptr, *pAl, *pC3, *pB1;
    static void *pW1h, *pW1l, *pW2h, *pW2l, *pW3h, *pW3l;
    if (!pAh) {
        cudaGetSymbolAddress(&pAh, g_Ah);   cudaGetSymbolAddress(&pAl, g_Al);
        cudaGetSymbolAddress(&pC3, g_C3);   cudaGetSymbolAddress(&pB1, g_bias1);
        cudaGetSymbolAddress(&pW1h, g_W1h); cudaGetSymbolAddress(&pW1l, g_W1l);
        cudaGetSymbolAddress(&pW2h, g_W2h); cudaGetSymbolAddress(&pW2l, g_W2l);
        cudaGetSymbolAddress(&pW3h, g_W3h); cudaGetSymbolAddress(&pW3l, g_W3l);
    }

    wprep_kernel<<<(KA * Hv + 2 * Hv * Hv + 255) / 256, 256>>>(W1, W2, W3);
    bias1_kernel<<<128, 128, 66048>>>(hV, W1, b1);
    geoA_kernel<<<NSITE, 128>>>(hE, Xn, Wp, bp);

    fusedgemm_kernel<<<MROWS / 128, 256, GEMM_SMEM>>>(
        (const __nv_bfloat16*)pAh, (const __nv_bfloat16*)pAl,
        (const __nv_bfloat16*)pW1h, (const __nv_bfloat16*)pW1l,
        (const __nv_bfloat16*)pW2h, (const __nv_bfloat16*)pW2l,
        (const __nv_bfloat16*)pW3h, (const __nv_bfloat16*)pW3l,
        (const float*)pB1, b2, b3, (float*)pC3);

    final_kernel<<<NSITE / SPB, 128>>>(hV, maskV, maskA, Wi, bi, Wo, bo,
                                       g1, be1, g2, be2, out);
}

// round 5
// speedup vs baseline: 2.2365x; 1.1411x over previous
#include <cuda_runtime.h>
#include <cuda_bf16.h>
#include <math.h>

#define Bv 8
#define Lv 512
#define Kv 30
#define Hv 128
#define NINv 384
#define FEATv 72
#define EPSv 1e-8f

#define NSITE (Bv * Lv)          // 4096
#define MROWS (NSITE * Kv)       // 122880
#define KA 480                   // padded A width: 384 hE + 72 feats + 24 zero
#define FCOL 384

// ------------------------- global scratch (static, no allocs) -------------
__device__ __nv_bfloat16 g_Ah[(size_t)MROWS * KA];
__device__ __nv_bfloat16 g_Al[(size_t)MROWS * KA];
__device__ float g_C3[(size_t)MROWS * Hv];
__device__ float g_bias1[(size_t)NSITE * Hv];
__device__ __nv_bfloat16 g_W1h[KA * Hv], g_W1l[KA * Hv];
__device__ __nv_bfloat16 g_W2h[Hv * Hv], g_W2l[Hv * Hv];
__device__ __nv_bfloat16 g_W3h[Hv * Hv], g_W3l[Hv * Hv];

__device__ __forceinline__ float geluf(float x) {
    return 0.5f * x * (1.0f + erff(x * 0.7071067811865476f));
}
__device__ __forceinline__ void bsplit(float x, __nv_bfloat16& h, __nv_bfloat16& l) {
    h = __float2bfloat16(x);
    l = __float2bfloat16(x - __bfloat162float(h));
}
__device__ __forceinline__ unsigned packsplit_h(float a, float b) {
    __nv_bfloat162 v; v.x = __float2bfloat16(a); v.y = __float2bfloat16(b);
    return *(unsigned*)&v;
}
__device__ __forceinline__ unsigned packsplit_l(float a, float b) {
    __nv_bfloat16 ha = __float2bfloat16(a), hb = __float2bfloat16(b);
    __nv_bfloat162 v;
    v.x = __float2bfloat16(a - __bfloat162float(ha));
    v.y = __float2bfloat16(b - __bfloat162float(hb));
    return *(unsigned*)&v;
}

// ------------------------- small prep kernels -----------------------------
__global__ void wprep_kernel(const float* __restrict__ W1,
                             const float* __restrict__ W2,
                             const float* __restrict__ W3) {
    int idx = blockIdx.x * 256 + threadIdx.x;
    if (idx < KA * Hv) {
        int j = idx / Hv, c = idx % Hv;
        float v = (j < 456) ? W1[(Hv + j) * Hv + c] : 0.0f;
        bsplit(v, g_W1h[idx], g_W1l[idx]);
    } else if (idx < KA * Hv + Hv * Hv) {
        int i2 = idx - KA * Hv;
        bsplit(W2[i2], g_W2h[i2], g_W2l[i2]);
    } else if (idx < KA * Hv + 2 * Hv * Hv) {
        int i3 = idx - KA * Hv - Hv * Hv;
        bsplit(W3[i3], g_W3h[i3], g_W3l[i3]);
    }
}

// node-term bias: bias1[site][c] = b1[c] + sum_r hV[site,r] * W1[r,c]  (exact fp32)
__global__ __launch_bounds__(128) void bias1_kernel(const float* __restrict__ hV,
                                                    const float* __restrict__ W1,
                                                    const float* __restrict__ b1) {
    extern __shared__ float bsm[];
    float* sW = bsm;
    float* shv = bsm + 16384;
    int c = threadIdx.x;
    for (int i = c; i < 16384; i += 128) sW[i] = W1[i];
    __syncthreads();
    for (int site = blockIdx.x; site < NSITE; site += gridDim.x) {
        shv[c] = hV[(size_t)site * Hv + c];
        __syncthreads();
        float acc = b1[c];
        #pragma unroll 8
        for (int r = 0; r < Hv; r++) acc = fmaf(shv[r], sW[r * Hv + c], acc);
        g_bias1[(size_t)site * Hv + c] = acc;
        __syncthreads();
    }
}

__device__ __forceinline__ void make_frame(const float* __restrict__ x,
                                           float* __restrict__ R,
                                           float* __restrict__ t) {
    float Nx = x[0], Ny = x[1], Nz = x[2];
    float CAx = x[3], CAy = x[4], CAz = x[5];
    float Cx = x[6], Cy = x[7], Cz = x[8];
    float e0x = CAx - Nx, e0y = CAy - Ny, e0z = CAz - Nz;
    float inv = 1.0f / sqrtf(e0x * e0x + e0y * e0y + e0z * e0z + EPSv);
    e0x *= inv; e0y *= inv; e0z *= inv;
    float e1x = Cx - CAx, e1y = Cy - CAy, e1z = Cz - CAz;
    float d = e0x * e1x + e0y * e1y + e0z * e1z;
    e1x -= e0x * d; e1y -= e0y * d; e1z -= e0z * d;
    inv = 1.0f / sqrtf(e1x * e1x + e1y * e1y + e1z * e1z + EPSv);
    e1x *= inv; e1y *= inv; e1z *= inv;
    float e2x = e0y * e1z - e0z * e1y;
    float e2y = e0z * e1x - e0x * e1z;
    float e2z = e0x * e1y - e0y * e1x;
    R[0] = e0x; R[1] = e1x; R[2] = e2x;
    R[3] = e0y; R[4] = e1y; R[5] = e2y;
    R[6] = e0z; R[7] = e1z; R[8] = e2z;
    t[0] = CAx; t[1] = CAy; t[2] = CAz;
}

// ---------------------------------------------------------------------------
// geoA: stage hE tile in smem, geometry + split-bf16 A rows. One site/block.
// smem floats: hE[30*385]=11550 | Wp 3072 | pln 720 | R 270 | T 90 | npg 720 | feat 2160
// ---------------------------------------------------------------------------
#define GO_HE   0
#define GO_WP   11550
#define GO_PLN  14622
#define GO_R    15342
#define GO_T    15612
#define GO_NPG  15702
#define GO_FEAT 16422
#define GEOA_SMEM ((16422 + 2160) * 4)   // 74328 bytes

__global__ void __launch_bounds__(128) geoA_kernel(
    const float* __restrict__ hE,
    const float* __restrict__ Xn,
    const float* __restrict__ Wp,
    const float* __restrict__ bp)
{
    extern __shared__ float gs[];
    int bl = blockIdx.x;
    int tid = threadIdx.x;

    // stage hE tile (stride 385 for conflict-free column access) + Wp
    const float* src = hE + (size_t)bl * Kv * NINv;
    for (int i = tid; i < Kv * NINv; i += 128) {
        int k = i / NINv, j = i - k * NINv;
        gs[GO_HE + k * 385 + j] = src[i];
    }
    for (int i = tid; i < 128 * 24; i += 128) gs[GO_WP + i] = Wp[i];
    if (tid < Kv) make_frame(Xn + ((size_t)bl * Kv + tid) * 9,
                             gs + GO_R + tid * 9, gs + GO_T + tid * 3);
    __syncthreads();

    // p_ln[30][24]: thread (k = tid%30, g = tid/30) computes cols g*6..g*6+5
    if (tid < 120) {
        int k = tid % 30, g = tid / 30;
        float acc[6];
        #pragma unroll
        for (int j = 0; j < 6; j++) acc[j] = bp[g * 6 + j];
        const float* e = gs + GO_HE + k * 385 + 256;
        const float* wbase = gs + GO_WP + g * 6;
        #pragma unroll 4
        for (int i = 0; i < 128; i++) {
            float h = e[i];
            const float* wr = wbase + i * 24;
            float2 w01 = *(const float2*)(wr);
            float2 w23 = *(const float2*)(wr + 2);
            float2 w45 = *(const float2*)(wr + 4);
            acc[0] = fmaf(h, w01.x, acc[0]);
            acc[1] = fmaf(h, w01.y, acc[1]);
            acc[2] = fmaf(h, w23.x, acc[2]);
            acc[3] = fmaf(h, w23.y, acc[3]);
            acc[4] = fmaf(h, w45.x, acc[4]);
            acc[5] = fmaf(h, w45.y, acc[5]);
        }
        #pragma unroll
        for (int j = 0; j < 6; j++) gs[GO_PLN + k * 24 + g * 6 + j] = acc[j];
    }
    __syncthreads();

    // npg per edge (thread k)
    if (tid < Kv) {
        int k = tid;
        const float* R = gs + GO_R + k * 9;
        const float* t = gs + GO_T + k * 3;
        const float* pl = gs + GO_PLN + k * 24;
        #pragma unroll
        for (int n = 0; n < 8; n++)
            #pragma unroll
            for (int i = 0; i < 3; i++)
                gs[GO_NPG + k * 24 + n * 3 + i] =
                    t[i] + R[i * 3] * pl[n * 3] + R[i * 3 + 1] * pl[n * 3 + 1]
                         + R[i * 3 + 2] * pl[n * 3 + 2];
    }
    __syncthreads();

    // feats per edge: [ple 0..23 | pln 24..31 | npl 32..55 | npl_n 56..63 | npg_n 64..71]
    if (tid < Kv) {
        int k = tid;
        float* f = gs + GO_FEAT + k * 72;
        const float* pl0 = gs + GO_PLN;         // p_local = edge-0 p_ln
        const float* pg  = gs + GO_NPG;         // p_global = edge-0 npg
        const float* R0  = gs + GO_R;
        const float* t0  = gs + GO_T;
        const float* ng  = gs + GO_NPG + k * 24;
        #pragma unroll
        for (int n = 0; n < 8; n++) {
            float p0 = pl0[n * 3], p1 = pl0[n * 3 + 1], p2 = pl0[n * 3 + 2];
            f[n * 3] = p0; f[n * 3 + 1] = p1; f[n * 3 + 2] = p2;
            f[24 + n] = sqrtf(p0 * p0 + p1 * p1 + p2 * p2 + EPSv);
            float d0 = ng[n * 3]     - t0[0];
            float d1 = ng[n * 3 + 1] - t0[1];
            float d2 = ng[n * 3 + 2] - t0[2];
            float n0 = R0[0] * d0 + R0[3] * d1 + R0[6] * d2;   // R0^T row i=0
            float n1 = R0[1] * d0 + R0[4] * d1 + R0[7] * d2;
            float n2 = R0[2] * d0 + R0[5] * d1 + R0[8] * d2;
            f[32 + n * 3] = n0; f[32 + n * 3 + 1] = n1; f[32 + n * 3 + 2] = n2;
            f[56 + n] = sqrtf(n0 * n0 + n1 * n1 + n2 * n2 + EPSv);
            float gx = pg[n * 3]     - ng[n * 3];
            float gy = pg[n * 3 + 1] - ng[n * 3 + 1];
            float gz = pg[n * 3 + 2] - ng[n * 3 + 2];
            f[64 + n] = sqrtf(gx * gx + gy * gy + gz * gz + EPSv);
        }
    }
    __syncthreads();

    // write A (packed bf16x2 pair stores)
    size_t base_row = (size_t)bl * Kv;
    for (int p = tid; p < Kv * (KA / 2); p += 128) {
        int k = p / (KA / 2), j2 = p - k * (KA / 2);
        int col = j2 * 2;
        float v0 = (col < 384) ? gs[GO_HE + k * 385 + col]
                 : (col < 456) ? gs[GO_FEAT + k * 72 + col - 384] : 0.0f;
        float v1 = (col + 1 < 384) ? gs[GO_HE + k * 385 + col + 1]
                 : (col + 1 < 456) ? gs[GO_FEAT + k * 72 + col + 1 - 384] : 0.0f;
        __nv_bfloat16 h0, l0, h1, l1;
        bsplit(v0, h0, l0); bsplit(v1, h1, l1);
        size_t o = (base_row + k) * KA + col;
        __nv_bfloat162 hh; hh.x = h0; hh.y = h1;
        __nv_bfloat162 ll; ll.x = l0; ll.y = l1;
        *(__nv_bfloat162*)(g_Ah + o) = hh;
        *(__nv_bfloat162*)(g_Al + o) = ll;
    }
}

// ---------------------------------------------------------------------------
// Fused GEMM: C3 = gelu(gelu(A@W1 + bias1)@W2 + b2)@W3 + b3 ; split-bf16 3-pass.
// 256 thr, M-tile 128, 2-stage pipeline, W2/W3 loaded into stage space after
// phase 1, low-split A fragments spilled to smem -> 128 regs, 2 CTAs/SM.
// ---------------------------------------------------------------------------
#define OFF_AH 0
#define OFF_AL 10240
#define OFF_BH 20480
#define OFF_BL 29184
#define STAGE_BYTES 37888
#define OFF_W2H 0
#define OFF_W2L 34816
#define OFF_SPILL (2 * STAGE_BYTES)            // 75776
#define GEMM_SMEM (OFF_SPILL + 32768)          // 108544

__device__ __forceinline__ void cpasync16(unsigned dst, const void* src) {
    asm volatile("cp.async.cg.shared.global [%0], [%1], 16;\n" :: "r"(dst), "l"(src));
}
__device__ __forceinline__ void ldm_x4(unsigned* r, unsigned addr) {
    asm volatile("ldmatrix.sync.aligned.m8n8.x4.shared.b16 {%0,%1,%2,%3}, [%4];"
        : "=r"(r[0]), "=r"(r[1]), "=r"(r[2]), "=r"(r[3]) : "r"(addr));
}
__device__ __forceinline__ void ldm_x4_t(unsigned* r, unsigned addr) {
    asm volatile("ldmatrix.sync.aligned.m8n8.x4.trans.shared.b16 {%0,%1,%2,%3}, [%4];"
        : "=r"(r[0]), "=r"(r[1]), "=r"(r[2]), "=r"(r[3]) : "r"(addr));
}
__device__ __forceinline__ void mma_bf16(float* d, const unsigned* a, unsigned b0, unsigned b1) {
    asm volatile("mma.sync.aligned.m16n8k16.row.col.f32.bf16.bf16.f32 "
        "{%0,%1,%2,%3}, {%4,%5,%6,%7}, {%8,%9}, {%0,%1,%2,%3};"
        : "+f"(d[0]), "+f"(d[1]), "+f"(d[2]), "+f"(d[3])
        : "r"(a[0]), "r"(a[1]), "r"(a[2]), "r"(a[3]), "r"(b0), "r"(b1));
}
__device__ __forceinline__ void sts128(unsigned addr, const unsigned* v) {
    asm volatile("st.shared.v4.b32 [%0], {%1,%2,%3,%4};"
        :: "r"(addr), "r"(v[0]), "r"(v[1]), "r"(v[2]), "r"(v[3]));
}
__device__ __forceinline__ void lds128(unsigned* v, unsigned addr) {
    asm volatile("ld.shared.v4.b32 {%0,%1,%2,%3}, [%4];"
        : "=r"(v[0]), "=r"(v[1]), "=r"(v[2]), "=r"(v[3]) : "r"(addr));
}

__device__ __forceinline__ void gemm_load_chunk(
    unsigned sb, const __nv_bfloat16* __restrict__ Ah, const __nv_bfloat16* __restrict__ Al,
    const __nv_bfloat16* __restrict__ Bh, const __nv_bfloat16* __restrict__ Bl,
    int rowBase, int kc, int tid)
{
    #pragma unroll
    for (int i = 0; i < 2; i++) {
        int tt = tid + i * 256;
        int row = tt >> 2, seg = tt & 3;
        const __nv_bfloat16* ga = Ah + (size_t)(rowBase + row) * KA + kc + seg * 8;
        cpasync16(sb + OFF_AH + (row * 40 + seg * 8) * 2, ga);
        ga = Al + (size_t)(rowBase + row) * KA + kc + seg * 8;
        cpasync16(sb + OFF_AL + (row * 40 + seg * 8) * 2, ga);
        int rb = tt >> 4, sg = tt & 15;
        const __nv_bfloat16* gb = Bh + (size_t)(kc + rb) * Hv + sg * 8;
        cpasync16(sb + OFF_BH + (rb * 136 + sg * 8) * 2, gb);
        gb = Bl + (size_t)(kc + rb) * Hv + sg * 8;
        cpasync16(sb + OFF_BL + (rb * 136 + sg * 8) * 2, gb);
    }
    asm volatile("cp.async.commit_group;\n" ::);
}

__device__ __forceinline__ void load_weight(unsigned sbase, unsigned off,
                                            const __nv_bfloat16* __restrict__ src, int tid) {
    #pragma unroll
    for (int i = 0; i < 8; i++) {
        int idx = tid + i * 256;
        int r = idx >> 4, s = idx & 15;
        cpasync16(sbase + off + (r * 136 + s * 8) * 2, src + r * Hv + s * 8);
    }
}

__global__ __launch_bounds__(256, 2) void fusedgemm_kernel(
    const __nv_bfloat16* __restrict__ Ah, const __nv_bfloat16* __restrict__ Al,
    const __nv_bfloat16* __restrict__ W1h, const __nv_bfloat16* __restrict__ W1l,
    const __nv_bfloat16* __restrict__ W2h, const __nv_bfloat16* __restrict__ W2l,
    const __nv_bfloat16* __restrict__ W3h, const __nv_bfloat16* __restrict__ W3l,
    const float* __restrict__ bias1,
    const float* __restrict__ b2, const float* __restrict__ b3,
    float* __restrict__ C3)
{
    extern __shared__ __align__(16) unsigned char gsm[];
    unsigned sbase = (unsigned)__cvta_generic_to_shared(gsm);

    int tid = threadIdx.x;
    int lane = tid & 31, w = tid >> 5;
    int rowBase = blockIdx.x * 128;
    unsigned spill_base = sbase + OFF_SPILL + w * 4096 + lane * 16;

    float acc[16][4];
    #pragma unroll
    for (int t = 0; t < 16; t++)
        #pragma unroll
        for (int q = 0; q < 4; q++) acc[t][q] = 0.0f;

    const int nch = KA / 32;   // 15

    gemm_load_chunk(sbase, Ah, Al, W1h, W1l, rowBase, 0, tid);
    gemm_load_chunk(sbase + STAGE_BYTES, Ah, Al, W1h, W1l, rowBase, 32, tid);

    // -------- phase 1: A @ W1 (K = 480), 2-stage --------
    for (int c = 0; c < nch; c++) {
        if (c + 1 < nch) { asm volatile("cp.async.wait_group 1;\n" ::); }
        else             { asm volatile("cp.async.wait_group 0;\n" ::); }
        __syncthreads();

        unsigned sb = sbase + (c & 1) * STAGE_BYTES;
        #pragma unroll
        for (int kk = 0; kk < 32; kk += 16) {
            unsigned aH[4], aL[4];
            {
                int row = w * 16 + (lane & 15);
                unsigned off = (unsigned)((row * 40 + kk + ((lane >> 4) << 3)) * 2);
                ldm_x4(aH, sb + OFF_AH + off);
                ldm_x4(aL, sb + OFF_AL + off);
            }
            #pragma unroll
            for (int nb = 0; nb < 8; nb++) {
                unsigned offb = (unsigned)(((kk + (lane & 15)) * 136 + nb * 16 + ((lane >> 4) << 3)) * 2);
                unsigned bh[4], bl[4];
                ldm_x4_t(bh, sb + OFF_BH + offb);
                ldm_x4_t(bl, sb + OFF_BL + offb);
                mma_bf16(acc[2 * nb],     aH, bh[0], bh[1]);
                mma_bf16(acc[2 * nb],     aH, bl[0], bl[1]);
                mma_bf16(acc[2 * nb],     aL, bh[0], bh[1]);
                mma_bf16(acc[2 * nb + 1], aH, bh[2], bh[3]);
                mma_bf16(acc[2 * nb + 1], aH, bl[2], bl[3]);
                mma_bf16(acc[2 * nb + 1], aL, bh[2], bh[3]);
            }
        }
        __syncthreads();
        if (c + 2 < nch)
            gemm_load_chunk(sbase + (c & 1) * STAGE_BYTES, Ah, Al, W1h, W1l,
                            rowBase, (c + 2) * 32, tid);
    }

    // W2 into freed stage space (overlaps epilogue math)
    load_weight(sbase, OFF_W2H, W2h, tid);
    load_weight(sbase, OFF_W2L, W2l, tid);
    asm volatile("cp.async.commit_group;\n" ::);

    // phase-1 epilogue: + bias1(site), gelu, split: highs in regs, lows to smem
    int r0 = w * 16 + (lane >> 2);
    int r1 = r0 + 8;
    const float* bs0 = bias1 + (size_t)((rowBase + r0) / Kv) * Hv;
    const float* bs1 = bias1 + (size_t)((rowBase + r1) / Kv) * Hv;

    unsigned a_h[16][2];
    #pragma unroll
    for (int q = 0; q < 8; q++) {
        unsigned lo[4];
        #pragma unroll
        for (int h2 = 0; h2 < 2; h2++) {
            int t = 2 * q + h2;
            int col = t * 8 + ((lane & 3) << 1);
            float2 c0 = *(const float2*)(bs0 + col);
            float2 c1 = *(const float2*)(bs1 + col);
            float v00 = geluf(acc[t][0] + c0.x);
            float v01 = geluf(acc[t][1] + c0.y);
            float v10 = geluf(acc[t][2] + c1.x);
            float v11 = geluf(acc[t][3] + c1.y);
            a_h[t][0] = packsplit_h(v00, v01);
            lo[h2 * 2]     = packsplit_l(v00, v01);
            a_h[t][1] = packsplit_h(v10, v11);
            lo[h2 * 2 + 1] = packsplit_l(v10, v11);
            acc[t][0] = 0.0f; acc[t][1] = 0.0f; acc[t][2] = 0.0f; acc[t][3] = 0.0f;
        }
        sts128(spill_base + q * 512, lo);
    }
    asm volatile("cp.async.wait_group 0;\n" ::);
    __syncthreads();

    // -------- phase 2: C1 @ W2 --------
    #pragma unroll
    for (int q = 0; q < 8; q++) {
        unsigned aH[4] = { a_h[2 * q][0], a_h[2 * q][1], a_h[2 * q + 1][0], a_h[2 * q + 1][1] };
        unsigned aL[4];
        lds128(aL, spill_base + q * 512);
        #pragma unroll
        for (int nb = 0; nb < 8; nb++) {
            unsigned offb = (unsigned)(((q * 16 + (lane & 15)) * 136 + nb * 16 + ((lane >> 4) << 3)) * 2);
            unsigned bh[4], bl[4];
            ldm_x4_t(bh, sbase + OFF_W2H + offb);
            ldm_x4_t(bl, sbase + OFF_W2L + offb);
            mma_bf16(acc[2 * nb],     aH, bh[0], bh[1]);
            mma_bf16(acc[2 * nb],     aH, bl[0], bl[1]);
            mma_bf16(acc[2 * nb],     aL, bh[0], bh[1]);
            mma_bf16(acc[2 * nb + 1], aH, bh[2], bh[3]);
            mma_bf16(acc[2 * nb + 1], aH, bl[2], bl[3]);
            mma_bf16(acc[2 * nb + 1], aL, bh[2], bh[3]);
        }
    }
    __syncthreads();   // all warps done reading W2
    load_weight(sbase, OFF_W2H, W3h, tid);
    load_weight(sbase, OFF_W2L, W3l, tid);
    asm volatile("cp.async.commit_group;\n" ::);

    // phase-2 epilogue: + b2, gelu, split
    #pragma unroll
    for (int q = 0; q < 8; q++) {
        unsigned lo[4];
        #pragma unroll
        for (int h2 = 0; h2 < 2; h2++) {
            int t = 2 * q + h2;
            int col = t * 8 + ((lane & 3) << 1);
            float2 bb = *(const float2*)(b2 + col);
            float v00 = geluf(acc[t][0] + bb.x);
            float v01 = geluf(acc[t][1] + bb.y);
            float v10 = geluf(acc[t][2] + bb.x);
            float v11 = geluf(acc[t][3] + bb.y);
            a_h[t][0] = packsplit_h(v00, v01);
            lo[h2 * 2]     = packsplit_l(v00, v01);
            a_h[t][1] = packsplit_h(v10, v11);
            lo[h2 * 2 + 1] = packsplit_l(v10, v11);
            acc[t][0] = 0.0f; acc[t][1] = 0.0f; acc[t][2] = 0.0f; acc[t][3] = 0.0f;
        }
        sts128(spill_base + q * 512, lo);
    }
    asm volatile("cp.async.wait_group 0;\n" ::);
    __syncthreads();

    // -------- phase 3: C2 @ W3 --------
    #pragma unroll
    for (int q = 0; q < 8; q++) {
        unsigned aH[4] = { a_h[2 * q][0], a_h[2 * q][1], a_h[2 * q + 1][0], a_h[2 * q + 1][1] };
        unsigned aL[4];
        lds128(aL, spill_base + q * 512);
        #pragma unroll
        for (int nb = 0; nb < 8; nb++) {
            unsigned offb = (unsigned)(((q * 16 + (lane & 15)) * 136 + nb * 16 + ((lane >> 4) << 3)) * 2);
            unsigned bh[4], bl[4];
            ldm_x4_t(bh, sbase + OFF_W2H + offb);
            ldm_x4_t(bl, sbase + OFF_W2L + offb);
            mma_bf16(acc[2 * nb],     aH, bh[0], bh[1]);
            mma_bf16(acc[2 * nb],     aH, bl[0], bl[1]);
            mma_bf16(acc[2 * nb],     aL, bh[0], bh[1]);
            mma_bf16(acc[2 * nb + 1], aH, bh[2], bh[3]);
            mma_bf16(acc[2 * nb + 1], aH, bl[2], bl[3]);
            mma_bf16(acc[2 * nb + 1], aL, bh[2], bh[3]);
        }
    }

    // final epilogue: + b3, store fp32 C3
    #pragma unroll
    for (int t = 0; t < 16; t++) {
        int col = t * 8 + ((lane & 3) << 1);
        float2 bb = *(const float2*)(b3 + col);
        float2 v0; v0.x = acc[t][0] + bb.x; v0.y = acc[t][1] + bb.y;
        float2 v1; v1.x = acc[t][2] + bb.x; v1.y = acc[t][3] + bb.y;
        *(float2*)(C3 + (size_t)(rowBase + r0) * Hv + col) = v0;
        *(float2*)(C3 + (size_t)(rowBase + r1) * Hv + col) = v1;
    }
}

// ---------------------------------------------------------------------------
// Final: masked mean over k + LN1 + FFN + LN2 + masked out. 8 sites/block.
// ---------------------------------------------------------------------------
#define SPB 8
__global__ __launch_bounds__(128) void final_kernel(
    const float* __restrict__ hV, const float* __restrict__ maskV,
    const float* __restrict__ maskA,
    const float* __restrict__ Wi, const float* __restrict__ bi,
    const float* __restrict__ Wo, const float* __restrict__ bo,
    const float* __restrict__ g1, const float* __restrict__ be1,
    const float* __restrict__ g2, const float* __restrict__ be2,
    float* __restrict__ out)
{
    __shared__ float s_h[SPB][Hv];
    __shared__ float s_f[SPB][4 * Hv];
    __shared__ float s_red[8];
    int c = threadIdx.x;
    int base_site = blockIdx.x * SPB;

    for (int s = 0; s < SPB; s++) {
        int site = base_site + s;
        const float* c3 = g_C3 + (size_t)site * Kv * Hv + c;
        const float* ma = maskA + (size_t)site * Kv;
        float nm = 0.0f;
        #pragma unroll
        for (int k = 0; k < Kv; k++) nm += c3[k * Hv] * ma[k];
        nm *= (1.0f / (float)Kv);
        float xv = hV[(size_t)site * Hv + c] + nm;
        float sum = xv, sq = xv * xv;
        #pragma unroll
        for (int o = 16; o; o >>= 1) {
            sum += __shfl_xor_sync(0xffffffffu, sum, o);
            sq  += __shfl_xor_sync(0xffffffffu, sq, o);
        }
        if ((c & 31) == 0) { s_red[c >> 5] = sum; s_red[4 + (c >> 5)] = sq; }
        __syncthreads();
        sum = s_red[0] + s_red[1] + s_red[2] + s_red[3];
        sq  = s_red[4] + s_red[5] + s_red[6] + s_red[7];
        float mean = sum * (1.0f / Hv);
        float var  = sq * (1.0f / Hv) - mean * mean;
        s_h[s][c] = (xv - mean) * rsqrtf(var + 1e-5f) * g1[c] + be1[c];
        __syncthreads();
    }

    float hi[SPB][4];
    #pragma unroll
    for (int s = 0; s < SPB; s++) {
        hi[s][0] = bi[c];        hi[s][1] = bi[c + 128];
        hi[s][2] = bi[c + 256];  hi[s][3] = bi[c + 384];
    }
    for (int r = 0; r < Hv; r++) {
        const float* wr = Wi + (size_t)r * 512;
        float w0 = wr[c], w1 = wr[c + 128], w2 = wr[c + 256], w3 = wr[c + 384];
        #pragma unroll
        for (int s = 0; s < SPB; s++) {
            float hv = s_h[s][r];
            hi[s][0] = fmaf(hv, w0, hi[s][0]);
            hi[s][1] = fmaf(hv, w1, hi[s][1]);
            hi[s][2] = fmaf(hv, w2, hi[s][2]);
            hi[s][3] = fmaf(hv, w3, hi[s][3]);
        }
    }
    #pragma unroll
    for (int s = 0; s < SPB; s++) {
        s_f[s][c]       = geluf(hi[s][0]);
        s_f[s][c + 128] = geluf(hi[s][1]);
        s_f[s][c + 256] = geluf(hi[s][2]);
        s_f[s][c + 384] = geluf(hi[s][3]);
    }
    __syncthreads();

    float d[SPB];
    #pragma unroll
    for (int s = 0; s < SPB; s++) d[s] = bo[c];
    for (int j = 0; j < 512; j++) {
        float w = Wo[(size_t)j * Hv + c];
        #pragma unroll
        for (int s = 0; s < SPB; s++) d[s] = fmaf(s_f[s][j], w, d[s]);
    }

    for (int s = 0; s < SPB; s++) {
        int site = base_site + s;
        float x2 = s_h[s][c] + d[s];
        float sum = x2, sq = x2 * x2;
        #pragma unroll
        for (int o = 16; o; o >>= 1) {
            sum += __shfl_xor_sync(0xffffffffu, sum, o);
            sq  += __shfl_xor_sync(0xffffffffu, sq, o);
        }
        if ((c & 31) == 0) { s_red[c >> 5] = sum; s_red[4 + (c >> 5)] = sq; }
        __syncthreads();
        sum = s_red[0] + s_red[1] + s_red[2] + s_red[3];
        sq  = s_red[4] + s_red[5] + s_red[6] + s_red[7];
        float mean = sum * (1.0f / Hv);
        float var  = sq * (1.0f / Hv) - mean * mean;
        float h2 = (x2 - mean) * rsqrtf(var + 1e-5f) * g2[c] + be2[c];
        out[(size_t)site * Hv + c] = maskV[site] * h2;
        __syncthreads();
    }
}

// ---------------------------------------------------------------------------

extern "C" void kernel_launch(void* const* d_in, const int* in_sizes, int n_in,
                              void* d_out, int out_size) {
    const float* hV    = (const float*)d_in[0];
    const float* hE    = (const float*)d_in[1];
    const float* Xn    = (const float*)d_in[3];
    const float* maskV = (const float*)d_in[4];
    const float* maskA = (const float*)d_in[5];
    const float* Wp    = (const float*)d_in[6];
    const float* bp    = (const float*)d_in[7];
    const float* W1    = (const float*)d_in[8];
    const float* b1    = (const float*)d_in[9];
    const float* W2    = (const float*)d_in[10];
    const float* b2    = (const float*)d_in[11];
    const float* W3    = (const float*)d_in[12];
    const float* b3    = (const float*)d_in[13];
    const float* Wi    = (const float*)d_in[14];
    const float* bi    = (const float*)d_in[15];
    const float* Wo    = (const float*)d_in[16];
    const float* bo    = (const float*)d_in[17];
    const float* g1    = (const float*)d_in[18];
    const float* be1   = (const float*)d_in[19];
    const float* g2    = (const float*)d_in[20];
    const float* be2   = (const float*)d_in[21];
    float* out = (float*)d_out;

    cudaFuncSetAttribute(fusedgemm_kernel, cudaFuncAttributeMaxDynamicSharedMemorySize, GEMM_SMEM);
    cudaFuncSetAttribute(bias1_kernel, cudaFuncAttributeMaxDynamicSharedMemorySize, 66048);
    cudaFuncSetAttribute(geoA_kernel, cudaFuncAttributeMaxDynamicSharedMemorySize, GEOA_SMEM);

    static void *pAh = nullptr, *pAl, *pC3, *pB1;
    static void *pW1h, *pW1l, *pW2h, *pW2l, *pW3h, *pW3l;
    if (!pAh) {
        cudaGetSymbolAddress(&pAh, g_Ah);   cudaGetSymbolAddress(&pAl, g_Al);
        cudaGetSymbolAddress(&pC3, g_C3);   cudaGetSymbolAddress(&pB1, g_bias1);
        cudaGetSymbolAddress(&pW1h, g_W1h); cudaGetSymbolAddress(&pW1l, g_W1l);
        cudaGetSymbolAddress(&pW2h, g_W2h); cudaGetSymbolAddress(&pW2l, g_W2l);
        cudaGetSymbolAddress(&pW3h, g_W3h); cudaGetSymbolAddress(&pW3l, g_W3l);
    }

    wprep_kernel<<<(KA * Hv + 2 * Hv * Hv + 255) / 256, 256>>>(W1, W2, W3);
    bias1_kernel<<<512, 128, 66048>>>(hV, W1, b1);
    geoA_kernel<<<NSITE, 128, GEOA_SMEM>>>(hE, Xn, Wp, bp);

    fusedgemm_kernel<<<MROWS / 128, 256, GEMM_SMEM>>>(
        (const __nv_bfloat16*)pAh, (const __nv_bfloat16*)pAl,
        (const __nv_bfloat16*)pW1h, (const __nv_bfloat16*)pW1l,
        (const __nv_bfloat16*)pW2h, (const __nv_bfloat16*)pW2l,
        (const __nv_bfloat16*)pW3h, (const __nv_bfloat16*)pW3l,
        (const float*)pB1, b2, b3, (float*)pC3);

    final_kernel<<<NSITE / SPB, 128>>>(hV, maskV, maskA, Wi, bi, Wo, bo,
                                       g1, be1, g2, be2, out);
}

// round 6
// speedup vs baseline: 2.8357x; 1.2679x over previous
#include <cuda_runtime.h>
#include <cuda_bf16.h>
#include <math.h>

#define Bv 8
#define Lv 512
#define Kv 30
#define Hv 128
#define NINv 384
#define FEATv 72
#define EPSv 1e-8f

#define NSITE (Bv * Lv)          // 4096
#define MPAD (NSITE * 32)        // 131072 padded rows (32 edges/site)
#define KA 480                   // A width: 384 hE + 72 feats + 24 zero
#define NCH 15                   // 480/32 k-chunks

// ------------------------- global scratch (static, no allocs) -------------
__device__ float g_feat[(size_t)MPAD * 96];     // feats (A cols 384..479), fp32
__device__ float g_C3[(size_t)MPAD * Hv];
__device__ float g_bias1[(size_t)NSITE * Hv];
__device__ __nv_bfloat16 g_W1h[KA * Hv], g_W1l[KA * Hv];
__device__ __nv_bfloat16 g_W2h[Hv * Hv], g_W2l[Hv * Hv];
__device__ __nv_bfloat16 g_W3h[Hv * Hv], g_W3l[Hv * Hv];

__device__ __forceinline__ float geluf(float x) {
    return 0.5f * x * (1.0f + erff(x * 0.7071067811865476f));
}
__device__ __forceinline__ void bsplit(float x, __nv_bfloat16& h, __nv_bfloat16& l) {
    h = __float2bfloat16(x);
    l = __float2bfloat16(x - __bfloat162float(h));
}
__device__ __forceinline__ unsigned packsplit_h(float a, float b) {
    __nv_bfloat162 v; v.x = __float2bfloat16(a); v.y = __float2bfloat16(b);
    return *(unsigned*)&v;
}
__device__ __forceinline__ unsigned packsplit_l(float a, float b) {
    __nv_bfloat16 ha = __float2bfloat16(a), hb = __float2bfloat16(b);
    __nv_bfloat162 v;
    v.x = __float2bfloat16(a - __bfloat162float(ha));
    v.y = __float2bfloat16(b - __bfloat162float(hb));
    return *(unsigned*)&v;
}

// ------------------------- small prep kernels -----------------------------
__global__ void wprep_kernel(const float* __restrict__ W1,
                             const float* __restrict__ W2,
                             const float* __restrict__ W3) {
    int idx = blockIdx.x * 256 + threadIdx.x;
    if (idx < KA * Hv) {
        int j = idx / Hv, c = idx % Hv;
        float v = (j < 456) ? W1[(Hv + j) * Hv + c] : 0.0f;
        bsplit(v, g_W1h[idx], g_W1l[idx]);
    } else if (idx < KA * Hv + Hv * Hv) {
        int i2 = idx - KA * Hv;
        bsplit(W2[i2], g_W2h[i2], g_W2l[i2]);
    } else if (idx < KA * Hv + 2 * Hv * Hv) {
        int i3 = idx - KA * Hv - Hv * Hv;
        bsplit(W3[i3], g_W3h[i3], g_W3l[i3]);
    }
}

// node-term bias: bias1[site][c] = b1[c] + sum_r hV[site,r] * W1[r,c]  (exact fp32)
__global__ __launch_bounds__(128) void bias1_kernel(const float* __restrict__ hV,
                                                    const float* __restrict__ W1,
                                                    const float* __restrict__ b1) {
    extern __shared__ float bsm[];
    float* sW = bsm;
    float* shv = bsm + 16384;
    int c = threadIdx.x;
    for (int i = c; i < 16384; i += 128) sW[i] = W1[i];
    __syncthreads();
    for (int site = blockIdx.x; site < NSITE; site += gridDim.x) {
        shv[c] = hV[(size_t)site * Hv + c];
        __syncthreads();
        float acc = b1[c];
        #pragma unroll 8
        for (int r = 0; r < Hv; r++) acc = fmaf(shv[r], sW[r * Hv + c], acc);
        g_bias1[(size_t)site * Hv + c] = acc;
        __syncthreads();
    }
}

__device__ __forceinline__ void make_frame(const float* __restrict__ x,
                                           float* __restrict__ R,
                                           float* __restrict__ t) {
    float Nx = x[0], Ny = x[1], Nz = x[2];
    float CAx = x[3], CAy = x[4], CAz = x[5];
    float Cx = x[6], Cy = x[7], Cz = x[8];
    float e0x = CAx - Nx, e0y = CAy - Ny, e0z = CAz - Nz;
    float inv = 1.0f / sqrtf(e0x * e0x + e0y * e0y + e0z * e0z + EPSv);
    e0x *= inv; e0y *= inv; e0z *= inv;
    float e1x = Cx - CAx, e1y = Cy - CAy, e1z = Cz - CAz;
    float d = e0x * e1x + e0y * e1y + e0z * e1z;
    e1x -= e0x * d; e1y -= e0y * d; e1z -= e0z * d;
    inv = 1.0f / sqrtf(e1x * e1x + e1y * e1y + e1z * e1z + EPSv);
    e1x *= inv; e1y *= inv; e1z *= inv;
    float e2x = e0y * e1z - e0z * e1y;
    float e2y = e0z * e1x - e0x * e1z;
    float e2z = e0x * e1y - e0y * e1x;
    R[0] = e0x; R[1] = e1x; R[2] = e2x;
    R[3] = e0y; R[4] = e1y; R[5] = e2y;
    R[6] = e0z; R[7] = e1z; R[8] = e2z;
    t[0] = CAx; t[1] = CAy; t[2] = CAz;
}

// ---------------------------------------------------------------------------
// geoFeat: per-site geometry features -> g_feat fp32 [site*32+k][96]
// (cols 0..71 = ple,pln,npl,npl_norm,npg_norm; 72..95 = 0)
// ---------------------------------------------------------------------------
__global__ void __launch_bounds__(128) geoFeat_kernel(
    const float* __restrict__ hE,
    const float* __restrict__ Xn,
    const float* __restrict__ Wp,
    const float* __restrict__ bp)
{
    __shared__ float s_hvp[30 * 129];
    __shared__ float s_Wp[128 * 24];
    __shared__ float s_pln[30 * 24];
    __shared__ float s_R[30 * 9], s_T[30 * 3];
    __shared__ float s_npg[30 * 24];
    __shared__ float s_feat[30 * 72];

    int bl = blockIdx.x;
    int tid = threadIdx.x;

    for (int i = tid; i < 30 * 128; i += 128) {
        int k = i >> 7, j = i & 127;
        s_hvp[k * 129 + j] = hE[((size_t)(bl * Kv + k)) * NINv + 256 + j];
    }
    for (int i = tid; i < 128 * 24; i += 128) s_Wp[i] = Wp[i];
    if (tid < Kv) make_frame(Xn + ((size_t)(bl * Kv + tid)) * 9,
                             s_R + tid * 9, s_T + tid * 3);
    __syncthreads();

    // p_ln[30][24]
    if (tid < 120) {
        int k = tid % 30, g = tid / 30;
        float acc[6];
        #pragma unroll
        for (int j = 0; j < 6; j++) acc[j] = bp[g * 6 + j];
        const float* e = s_hvp + k * 129;
        const float* wbase = s_Wp + g * 6;
        #pragma unroll 4
        for (int i = 0; i < 128; i++) {
            float h = e[i];
            const float* wr = wbase + i * 24;
            float2 w01 = *(const float2*)(wr);
            float2 w23 = *(const float2*)(wr + 2);
            float2 w45 = *(const float2*)(wr + 4);
            acc[0] = fmaf(h, w01.x, acc[0]);
            acc[1] = fmaf(h, w01.y, acc[1]);
            acc[2] = fmaf(h, w23.x, acc[2]);
            acc[3] = fmaf(h, w23.y, acc[3]);
            acc[4] = fmaf(h, w45.x, acc[4]);
            acc[5] = fmaf(h, w45.y, acc[5]);
        }
        #pragma unroll
        for (int j = 0; j < 6; j++) s_pln[k * 24 + g * 6 + j] = acc[j];
    }
    __syncthreads();

    if (tid < Kv) {
        int k = tid;
        const float* R = s_R + k * 9;
        const float* t = s_T + k * 3;
        const float* pl = s_pln + k * 24;
        #pragma unroll
        for (int n = 0; n < 8; n++)
            #pragma unroll
            for (int i = 0; i < 3; i++)
                s_npg[k * 24 + n * 3 + i] =
                    t[i] + R[i * 3] * pl[n * 3] + R[i * 3 + 1] * pl[n * 3 + 1]
                         + R[i * 3 + 2] * pl[n * 3 + 2];
    }
    __syncthreads();

    if (tid < Kv) {
        int k = tid;
        float* f = s_feat + k * 72;
        const float* pl0 = s_pln;
        const float* pg  = s_npg;
        const float* R0  = s_R;
        const float* t0  = s_T;
        const float* ng  = s_npg + k * 24;
        #pragma unroll
        for (int n = 0; n < 8; n++) {
            float p0 = pl0[n * 3], p1 = pl0[n * 3 + 1], p2 = pl0[n * 3 + 2];
            f[n * 3] = p0; f[n * 3 + 1] = p1; f[n * 3 + 2] = p2;
            f[24 + n] = sqrtf(p0 * p0 + p1 * p1 + p2 * p2 + EPSv);
            float d0 = ng[n * 3]     - t0[0];
            float d1 = ng[n * 3 + 1] - t0[1];
            float d2 = ng[n * 3 + 2] - t0[2];
            float n0 = R0[0] * d0 + R0[3] * d1 + R0[6] * d2;
            float n1 = R0[1] * d0 + R0[4] * d1 + R0[7] * d2;
            float n2 = R0[2] * d0 + R0[5] * d1 + R0[8] * d2;
            f[32 + n * 3] = n0; f[32 + n * 3 + 1] = n1; f[32 + n * 3 + 2] = n2;
            f[56 + n] = sqrtf(n0 * n0 + n1 * n1 + n2 * n2 + EPSv);
            float gx = pg[n * 3]     - ng[n * 3];
            float gy = pg[n * 3 + 1] - ng[n * 3 + 1];
            float gz = pg[n * 3 + 2] - ng[n * 3 + 2];
            f[64 + n] = sqrtf(gx * gx + gy * gy + gz * gz + EPSv);
        }
    }
    __syncthreads();

    // write fp32 feats (cols 72..95 zero)
    for (int i = tid; i < 30 * 96; i += 128) {
        int k = i / 96, col = i - k * 96;
        float v = (col < 72) ? s_feat[k * 72 + col] : 0.0f;
        g_feat[((size_t)(bl * 32 + k)) * 96 + col] = v;
    }
}

// ---------------------------------------------------------------------------
// Fused GEMM: reads hE fp32 + feats fp32 directly, converts to split-bf16 in
// kernel, then C3 = gelu(gelu(A@W1+bias1)@W2+b2)@W3 + b3.
// 256 thr, M-tile 128 = 4 sites x 32 padded edges. 2 CTAs/SM.
// smem: Abuf 2x20480 | Wst 2x17408 | spill 32768 ; W2/W3 reuse [0,69632)
// ---------------------------------------------------------------------------
#define ABUF(i)  ((i) * 20480)          // Ah at +0, Al at +10240
#define WST(i)   (40960 + (i) * 17408)  // Bh at +0,  Bl at +8704
#define OFF_W2H  0
#define OFF_W2L  34816
#define OFF_SPILL 75776
#define GEMM_SMEM (OFF_SPILL + 32768)   // 108544

__device__ __forceinline__ void cpasync16(unsigned dst, const void* src) {
    asm volatile("cp.async.cg.shared.global [%0], [%1], 16;\n" :: "r"(dst), "l"(src));
}
__device__ __forceinline__ void ldm_x4(unsigned* r, unsigned addr) {
    asm volatile("ldmatrix.sync.aligned.m8n8.x4.shared.b16 {%0,%1,%2,%3}, [%4];"
        : "=r"(r[0]), "=r"(r[1]), "=r"(r[2]), "=r"(r[3]) : "r"(addr));
}
__device__ __forceinline__ void ldm_x4_t(unsigned* r, unsigned addr) {
    asm volatile("ldmatrix.sync.aligned.m8n8.x4.trans.shared.b16 {%0,%1,%2,%3}, [%4];"
        : "=r"(r[0]), "=r"(r[1]), "=r"(r[2]), "=r"(r[3]) : "r"(addr));
}
__device__ __forceinline__ void mma_bf16(float* d, const unsigned* a, unsigned b0, unsigned b1) {
    asm volatile("mma.sync.aligned.m16n8k16.row.col.f32.bf16.bf16.f32 "
        "{%0,%1,%2,%3}, {%4,%5,%6,%7}, {%8,%9}, {%0,%1,%2,%3};"
        : "+f"(d[0]), "+f"(d[1]), "+f"(d[2]), "+f"(d[3])
        : "r"(a[0]), "r"(a[1]), "r"(a[2]), "r"(a[3]), "r"(b0), "r"(b1));
}
__device__ __forceinline__ void sts128(unsigned addr, const unsigned* v) {
    asm volatile("st.shared.v4.b32 [%0], {%1,%2,%3,%4};"
        :: "r"(addr), "r"(v[0]), "r"(v[1]), "r"(v[2]), "r"(v[3]));
}
__device__ __forceinline__ void lds128(unsigned* v, unsigned addr) {
    asm volatile("ld.shared.v4.b32 {%0,%1,%2,%3}, [%4];"
        : "=r"(v[0]), "=r"(v[1]), "=r"(v[2]), "=r"(v[3]) : "r"(addr));
}

// W1 k-chunk loader: 32 rows of W1h/W1l into WST(st)
__device__ __forceinline__ void wload_chunk(unsigned sbase, int st,
                                            const __nv_bfloat16* __restrict__ W1h,
                                            const __nv_bfloat16* __restrict__ W1l,
                                            int kc, int tid) {
    unsigned wst = sbase + WST(st);
    #pragma unroll
    for (int i = 0; i < 2; i++) {
        int tt = tid + i * 256;
        int rb = tt >> 4, sg = tt & 15;
        cpasync16(wst + (rb * 136 + sg * 8) * 2, W1h + (size_t)(kc + rb) * Hv + sg * 8);
        cpasync16(wst + 8704 + (rb * 136 + sg * 8) * 2, W1l + (size_t)(kc + rb) * Hv + sg * 8);
    }
    asm volatile("cp.async.commit_group;\n" ::);
}

// Full 128x128 weight into [off, off+34816)
__device__ __forceinline__ void load_weight(unsigned sbase, unsigned off,
                                            const __nv_bfloat16* __restrict__ src, int tid) {
    #pragma unroll
    for (int i = 0; i < 8; i++) {
        int idx = tid + i * 256;
        int r = idx >> 4, s = idx & 15;
        cpasync16(sbase + off + (r * 136 + s * 8) * 2, src + (size_t)r * Hv + s * 8);
    }
}

__global__ __launch_bounds__(256, 2) void fusedgemm_kernel(
    const float* __restrict__ hE, const float* __restrict__ feat,
    const __nv_bfloat16* __restrict__ W1h, const __nv_bfloat16* __restrict__ W1l,
    const __nv_bfloat16* __restrict__ W2h, const __nv_bfloat16* __restrict__ W2l,
    const __nv_bfloat16* __restrict__ W3h, const __nv_bfloat16* __restrict__ W3l,
    const float* __restrict__ bias1,
    const float* __restrict__ b2, const float* __restrict__ b3,
    float* __restrict__ C3)
{
    extern __shared__ __align__(16) unsigned char gsm[];
    unsigned sbase = (unsigned)__cvta_generic_to_shared(gsm);

    int tid = threadIdx.x;
    int lane = tid & 31, w = tid >> 5;
    int rowBase = blockIdx.x * 128;
    unsigned spill_base = sbase + OFF_SPILL + w * 4096 + lane * 16;

    // A loader identity: thread covers row arow, 16 cols starting at half*16
    int arow = tid >> 1, half = tid & 1;
    int gr = rowBase + arow;
    int asite = gr >> 5;
    int ak = gr & 31; if (ak > 29) ak = 29;   // clamp padded rows to valid data
    const float* hE_row = hE + ((size_t)(asite * Kv + ak)) * NINv + half * 16;
    const float* ft_row = feat + ((size_t)(asite * 32 + ak)) * 96 + half * 16;

    float4 f0, f1, f2, f3;
    #define LDA(cc) do { \
        const float4* s4 = (const float4*)(((cc) < 12) ? (hE_row + (cc) * 32) \
                                                       : (ft_row + ((cc) - 12) * 32)); \
        f0 = s4[0]; f1 = s4[1]; f2 = s4[2]; f3 = s4[3]; \
    } while (0)

    #define CVTSTS(buf) do { \
        unsigned uh[8], ul[8]; \
        uh[0] = packsplit_h(f0.x, f0.y); ul[0] = packsplit_l(f0.x, f0.y); \
        uh[1] = packsplit_h(f0.z, f0.w); ul[1] = packsplit_l(f0.z, f0.w); \
        uh[2] = packsplit_h(f1.x, f1.y); ul[2] = packsplit_l(f1.x, f1.y); \
        uh[3] = packsplit_h(f1.z, f1.w); ul[3] = packsplit_l(f1.z, f1.w); \
        uh[4] = packsplit_h(f2.x, f2.y); ul[4] = packsplit_l(f2.x, f2.y); \
        uh[5] = packsplit_h(f2.z, f2.w); ul[5] = packsplit_l(f2.z, f2.w); \
        uh[6] = packsplit_h(f3.x, f3.y); ul[6] = packsplit_l(f3.x, f3.y); \
        uh[7] = packsplit_h(f3.z, f3.w); ul[7] = packsplit_l(f3.z, f3.w); \
        unsigned ab = sbase + ABUF(buf) + (unsigned)((arow * 40 + half * 16) * 2); \
        sts128(ab, uh); sts128(ab + 16, uh + 4); \
        sts128(ab + 10240, ul); sts128(ab + 10240 + 16, ul + 4); \
    } while (0)

    float acc[16][4];
    #pragma unroll
    for (int t = 0; t < 16; t++)
        #pragma unroll
        for (int q = 0; q < 4; q++) acc[t][q] = 0.0f;

    // prologue
    wload_chunk(sbase, 0, W1h, W1l, 0, tid);
    wload_chunk(sbase, 1, W1h, W1l, 32, tid);
    LDA(0);
    CVTSTS(0);

    // -------- phase 1: A @ W1, K=480, in-kernel fp32->split-bf16 --------
    for (int c = 0; c < NCH; c++) {
        if (c + 1 < NCH) { asm volatile("cp.async.wait_group 1;\n" ::); }
        else             { asm volatile("cp.async.wait_group 0;\n" ::); }
        __syncthreads();

        if (c + 1 < NCH) LDA(c + 1);

        unsigned abuf = sbase + ABUF(c & 1);
        unsigned wst  = sbase + WST(c & 1);
        #pragma unroll
        for (int kk = 0; kk < 32; kk += 16) {
            unsigned aH[4], aL[4];
            {
                int row = w * 16 + (lane & 15);
                unsigned off = (unsigned)((row * 40 + kk + ((lane >> 4) << 3)) * 2);
                ldm_x4(aH, abuf + off);
                ldm_x4(aL, abuf + 10240 + off);
            }
            #pragma unroll
            for (int nb = 0; nb < 8; nb++) {
                unsigned offb = (unsigned)(((kk + (lane & 15)) * 136 + nb * 16 + ((lane >> 4) << 3)) * 2);
                unsigned bh[4], bl[4];
                ldm_x4_t(bh, wst + offb);
                ldm_x4_t(bl, wst + 8704 + offb);
                mma_bf16(acc[2 * nb],     aH, bh[0], bh[1]);
                mma_bf16(acc[2 * nb],     aH, bl[0], bl[1]);
                mma_bf16(acc[2 * nb],     aL, bh[0], bh[1]);
                mma_bf16(acc[2 * nb + 1], aH, bh[2], bh[3]);
                mma_bf16(acc[2 * nb + 1], aH, bl[2], bl[3]);
                mma_bf16(acc[2 * nb + 1], aL, bh[2], bh[3]);
            }
        }

        if (c + 1 < NCH) CVTSTS((c + 1) & 1);
        __syncthreads();
        if (c + 2 < NCH) wload_chunk(sbase, c & 1, W1h, W1l, (c + 2) * 32, tid);
    }

    // W2 into [0, 69632) — all warps past final sync, region dead
    load_weight(sbase, OFF_W2H, W2h, tid);
    load_weight(sbase, OFF_W2L, W2l, tid);
    asm volatile("cp.async.commit_group;\n" ::);

    // phase-1 epilogue: + bias1(site), gelu, split (lows -> smem spill)
    int r0 = w * 16 + (lane >> 2);
    int r1 = r0 + 8;
    const float* bs0 = bias1 + (size_t)((rowBase + r0) >> 5) * Hv;
    const float* bs1 = bias1 + (size_t)((rowBase + r1) >> 5) * Hv;

    unsigned a_h[16][2];
    #pragma unroll
    for (int q = 0; q < 8; q++) {
        unsigned lo[4];
        #pragma unroll
        for (int h2 = 0; h2 < 2; h2++) {
            int t = 2 * q + h2;
            int col = t * 8 + ((lane & 3) << 1);
            float2 c0 = *(const float2*)(bs0 + col);
            float2 c1 = *(const float2*)(bs1 + col);
            float v00 = geluf(acc[t][0] + c0.x);
            float v01 = geluf(acc[t][1] + c0.y);
            float v10 = geluf(acc[t][2] + c1.x);
            float v11 = geluf(acc[t][3] + c1.y);
            a_h[t][0] = packsplit_h(v00, v01);
            lo[h2 * 2]     = packsplit_l(v00, v01);
            a_h[t][1] = packsplit_h(v10, v11);
            lo[h2 * 2 + 1] = packsplit_l(v10, v11);
            acc[t][0] = 0.0f; acc[t][1] = 0.0f; acc[t][2] = 0.0f; acc[t][3] = 0.0f;
        }
        sts128(spill_base + q * 512, lo);
    }
    asm volatile("cp.async.wait_group 0;\n" ::);
    __syncthreads();

    // -------- phase 2: C1 @ W2 --------
    #pragma unroll
    for (int q = 0; q < 8; q++) {
        unsigned aH[4] = { a_h[2 * q][0], a_h[2 * q][1], a_h[2 * q + 1][0], a_h[2 * q + 1][1] };
        unsigned aL[4];
        lds128(aL, spill_base + q * 512);
        #pragma unroll
        for (int nb = 0; nb < 8; nb++) {
            unsigned offb = (unsigned)(((q * 16 + (lane & 15)) * 136 + nb * 16 + ((lane >> 4) << 3)) * 2);
            unsigned bh[4], bl[4];
            ldm_x4_t(bh, sbase + OFF_W2H + offb);
            ldm_x4_t(bl, sbase + OFF_W2L + offb);
            mma_bf16(acc[2 * nb],     aH, bh[0], bh[1]);
            mma_bf16(acc[2 * nb],     aH, bl[0], bl[1]);
            mma_bf16(acc[2 * nb],     aL, bh[0], bh[1]);
            mma_bf16(acc[2 * nb + 1], aH, bh[2], bh[3]);
            mma_bf16(acc[2 * nb + 1], aH, bl[2], bl[3]);
            mma_bf16(acc[2 * nb + 1], aL, bh[2], bh[3]);
        }
    }
    __syncthreads();   // all warps done reading W2
    load_weight(sbase, OFF_W2H, W3h, tid);
    load_weight(sbase, OFF_W2L, W3l, tid);
    asm volatile("cp.async.commit_group;\n" ::);

    // phase-2 epilogue: + b2, gelu, split
    #pragma unroll
    for (int q = 0; q < 8; q++) {
        unsigned lo[4];
        #pragma unroll
        for (int h2 = 0; h2 < 2; h2++) {
            int t = 2 * q + h2;
            int col = t * 8 + ((lane & 3) << 1);
            float2 bb = *(const float2*)(b2 + col);
            float v00 = geluf(acc[t][0] + bb.x);
            float v01 = geluf(acc[t][1] + bb.y);
            float v10 = geluf(acc[t][2] + bb.x);
            float v11 = geluf(acc[t][3] + bb.y);
            a_h[t][0] = packsplit_h(v00, v01);
            lo[h2 * 2]     = packsplit_l(v00, v01);
            a_h[t][1] = packsplit_h(v10, v11);
            lo[h2 * 2 + 1] = packsplit_l(v10, v11);
            acc[t][0] = 0.0f; acc[t][1] = 0.0f; acc[t][2] = 0.0f; acc[t][3] = 0.0f;
        }
        sts128(spill_base + q * 512, lo);
    }
    asm volatile("cp.async.wait_group 0;\n" ::);
    __syncthreads();

    // -------- phase 3: C2 @ W3 --------
    #pragma unroll
    for (int q = 0; q < 8; q++) {
        unsigned aH[4] = { a_h[2 * q][0], a_h[2 * q][1], a_h[2 * q + 1][0], a_h[2 * q + 1][1] };
        unsigned aL[4];
        lds128(aL, spill_base + q * 512);
        #pragma unroll
        for (int nb = 0; nb < 8; nb++) {
            unsigned offb = (unsigned)(((q * 16 + (lane & 15)) * 136 + nb * 16 + ((lane >> 4) << 3)) * 2);
            unsigned bh[4], bl[4];
            ldm_x4_t(bh, sbase + OFF_W2H + offb);
            ldm_x4_t(bl, sbase + OFF_W2L + offb);
            mma_bf16(acc[2 * nb],     aH, bh[0], bh[1]);
            mma_bf16(acc[2 * nb],     aH, bl[0], bl[1]);
            mma_bf16(acc[2 * nb],     aL, bh[0], bh[1]);
            mma_bf16(acc[2 * nb + 1], aH, bh[2], bh[3]);
            mma_bf16(acc[2 * nb + 1], aH, bl[2], bl[3]);
            mma_bf16(acc[2 * nb + 1], aL, bh[2], bh[3]);
        }
    }

    // final epilogue: + b3, store fp32 C3
    #pragma unroll
    for (int t = 0; t < 16; t++) {
        int col = t * 8 + ((lane & 3) << 1);
        float2 bb = *(const float2*)(b3 + col);
        float2 v0; v0.x = acc[t][0] + bb.x; v0.y = acc[t][1] + bb.y;
        float2 v1; v1.x = acc[t][2] + bb.x; v1.y = acc[t][3] + bb.y;
        *(float2*)(C3 + (size_t)(rowBase + r0) * Hv + col) = v0;
        *(float2*)(C3 + (size_t)(rowBase + r1) * Hv + col) = v1;
    }
    #undef LDA
    #undef CVTSTS
}

// ---------------------------------------------------------------------------
// Final: masked mean over k + LN1 + FFN + LN2 + masked out. 8 sites/block.
// ---------------------------------------------------------------------------
#define SPB 8
__global__ __launch_bounds__(128) void final_kernel(
    const float* __restrict__ hV, const float* __restrict__ maskV,
    const float* __restrict__ maskA,
    const float* __restrict__ Wi, const float* __restrict__ bi,
    const float* __restrict__ Wo, const float* __restrict__ bo,
    const float* __restrict__ g1, const float* __restrict__ be1,
    const float* __restrict__ g2, const float* __restrict__ be2,
    float* __restrict__ out)
{
    __shared__ float s_h[SPB][Hv];
    __shared__ float s_f[SPB][4 * Hv];
    __shared__ float s_red[8];
    int c = threadIdx.x;
    int base_site = blockIdx.x * SPB;

    for (int s = 0; s < SPB; s++) {
        int site = base_site + s;
        const float* c3 = g_C3 + (size_t)site * 32 * Hv + c;   // padded stride
        const float* ma = maskA + (size_t)site * Kv;
        float nm = 0.0f;
        #pragma unroll
        for (int k = 0; k < Kv; k++) nm += c3[k * Hv] * ma[k];
        nm *= (1.0f / (float)Kv);
        float xv = hV[(size_t)site * Hv + c] + nm;
        float sum = xv, sq = xv * xv;
        #pragma unroll
        for (int o = 16; o; o >>= 1) {
            sum += __shfl_xor_sync(0xffffffffu, sum, o);
            sq  += __shfl_xor_sync(0xffffffffu, sq, o);
        }
        if ((c & 31) == 0) { s_red[c >> 5] = sum; s_red[4 + (c >> 5)] = sq; }
        __syncthreads();
        sum = s_red[0] + s_red[1] + s_red[2] + s_red[3];
        sq  = s_red[4] + s_red[5] + s_red[6] + s_red[7];
        float mean = sum * (1.0f / Hv);
        float var  = sq * (1.0f / Hv) - mean * mean;
        s_h[s][c] = (xv - mean) * rsqrtf(var + 1e-5f) * g1[c] + be1[c];
        __syncthreads();
    }

    float hi[SPB][4];
    #pragma unroll
    for (int s = 0; s < SPB; s++) {
        hi[s][0] = bi[c];        hi[s][1] = bi[c + 128];
        hi[s][2] = bi[c + 256];  hi[s][3] = bi[c + 384];
    }
    for (int r = 0; r < Hv; r++) {
        const float* wr = Wi + (size_t)r * 512;
        float w0 = wr[c], w1 = wr[c + 128], w2 = wr[c + 256], w3 = wr[c + 384];
        #pragma unroll
        for (int s = 0; s < SPB; s++) {
            float hv = s_h[s][r];
            hi[s][0] = fmaf(hv, w0, hi[s][0]);
            hi[s][1] = fmaf(hv, w1, hi[s][1]);
            hi[s][2] = fmaf(hv, w2, hi[s][2]);
            hi[s][3] = fmaf(hv, w3, hi[s][3]);
        }
    }
    #pragma unroll
    for (int s = 0; s < SPB; s++) {
        s_f[s][c]       = geluf(hi[s][0]);
        s_f[s][c + 128] = geluf(hi[s][1]);
        s_f[s][c + 256] = geluf(hi[s][2]);
        s_f[s][c + 384] = geluf(hi[s][3]);
    }
    __syncthreads();

    float d[SPB];
    #pragma unroll
    for (int s = 0; s < SPB; s++) d[s] = bo[c];
    for (int j = 0; j < 512; j++) {
        float w = Wo[(size_t)j * Hv + c];
        #pragma unroll
        for (int s = 0; s < SPB; s++) d[s] = fmaf(s_f[s][j], w, d[s]);
    }

    for (int s = 0; s < SPB; s++) {
        int site = base_site + s;
        float x2 = s_h[s][c] + d[s];
        float sum = x2, sq = x2 * x2;
        #pragma unroll
        for (int o = 16; o; o >>= 1) {
            sum += __shfl_xor_sync(0xffffffffu, sum, o);
            sq  += __shfl_xor_sync(0xffffffffu, sq, o);
        }
        if ((c & 31) == 0) { s_red[c >> 5] = sum; s_red[4 + (c >> 5)] = sq; }
        __syncthreads();
        sum = s_red[0] + s_red[1] + s_red[2] + s_red[3];
        sq  = s_red[4] + s_red[5] + s_red[6] + s_red[7];
        float mean = sum * (1.0f / Hv);
        float var  = sq * (1.0f / Hv) - mean * mean;
        float h2 = (x2 - mean) * rsqrtf(var + 1e-5f) * g2[c] + be2[c];
        out[(size_t)site * Hv + c] = maskV[site] * h2;
        __syncthreads();
    }
}

// ---------------------------------------------------------------------------

extern "C" void kernel_launch(void* const* d_in, const int* in_sizes, int n_in,
                              void* d_out, int out_size) {
    const float* hV    = (const float*)d_in[0];
    const float* hE    = (const float*)d_in[1];
    const float* Xn    = (const float*)d_in[3];
    const float* maskV = (const float*)d_in[4];
    const float* maskA = (const float*)d_in[5];
    const float* Wp    = (const float*)d_in[6];
    const float* bp    = (const float*)d_in[7];
    const float* W1    = (const float*)d_in[8];
    const float* b1    = (const float*)d_in[9];
    const float* W2    = (const float*)d_in[10];
    const float* b2    = (const float*)d_in[11];
    const float* W3    = (const float*)d_in[12];
    const float* b3    = (const float*)d_in[13];
    const float* Wi    = (const float*)d_in[14];
    const float* bi    = (const float*)d_in[15];
    const float* Wo    = (const float*)d_in[16];
    const float* bo    = (const float*)d_in[17];
    const float* g1    = (const float*)d_in[18];
    const float* be1   = (const float*)d_in[19];
    const float* g2    = (const float*)d_in[20];
    const float* be2   = (const float*)d_in[21];
    float* out = (float*)d_out;

    cudaFuncSetAttribute(fusedgemm_kernel, cudaFuncAttributeMaxDynamicSharedMemorySize, GEMM_SMEM);
    cudaFuncSetAttribute(bias1_kernel, cudaFuncAttributeMaxDynamicSharedMemorySize, 66048);

    static void *pFeat = nullptr, *pC3, *pB1;
    static void *pW1h, *pW1l, *pW2h, *pW2l, *pW3h, *pW3l;
    if (!pFeat) {
        cudaGetSymbolAddress(&pFeat, g_feat);
        cudaGetSymbolAddress(&pC3, g_C3);   cudaGetSymbolAddress(&pB1, g_bias1);
        cudaGetSymbolAddress(&pW1h, g_W1h); cudaGetSymbolAddress(&pW1l, g_W1l);
        cudaGetSymbolAddress(&pW2h, g_W2h); cudaGetSymbolAddress(&pW2l, g_W2l);
        cudaGetSymbolAddress(&pW3h, g_W3h); cudaGetSymbolAddress(&pW3l, g_W3l);
    }

    wprep_kernel<<<(KA * Hv + 2 * Hv * Hv + 255) / 256, 256>>>(W1, W2, W3);
    bias1_kernel<<<512, 128, 66048>>>(hV, W1, b1);
    geoFeat_kernel<<<NSITE, 128>>>(hE, Xn, Wp, bp);

    fusedgemm_kernel<<<MPAD / 128, 256, GEMM_SMEM>>>(
        hE, (const float*)pFeat,
        (const __nv_bfloat16*)pW1h, (const __nv_bfloat16*)pW1l,
        (const __nv_bfloat16*)pW2h, (const __nv_bfloat16*)pW2l,
        (const __nv_bfloat16*)pW3h, (const __nv_bfloat16*)pW3l,
        (const float*)pB1, b2, b3, (float*)pC3);

    final_kernel<<<NSITE / SPB, 128>>>(hV, maskV, maskA, Wi, bi, Wo, bo,
                                       g1, be1, g2, be2, out);
}

// round 7
// speedup vs baseline: 3.4070x; 1.2014x over previous
#include <cuda_runtime.h>
#include <cuda_bf16.h>
#include <cuda_fp16.h>
#include <math.h>

#define Bv 8
#define Lv 512
#define Kv 30
#define Hv 128
#define NINv 384
#define FEATv 72
#define EPSv 1e-8f

#define NSITE (Bv * Lv)          // 4096
#define MPAD (NSITE * 32)        // 131072 padded rows (32 edges/site)
#define KA 480                   // A width: 384 hE + 72 feats + 24 zero
#define NCH 15                   // 480/32 k-chunks

// ------------------------- global scratch (static, no allocs) -------------
__device__ float g_feat[(size_t)MPAD * 96];     // feats (A cols 384..479), fp32
__device__ float g_C3[(size_t)MPAD * Hv];
__device__ float g_bias1[(size_t)NSITE * Hv];
__device__ __half g_W1f[KA * Hv];
__device__ __half g_W2f[Hv * Hv];
__device__ __half g_W3f[Hv * Hv];

__device__ __forceinline__ float geluf(float x) {
    return 0.5f * x * (1.0f + erff(x * 0.7071067811865476f));
}
// pack two floats as fp16x2 (high part)
__device__ __forceinline__ unsigned pack2h(float a, float b) {
    __half2 v = __floats2half2_rn(a, b);
    return *(unsigned*)&v;
}
// pack two fp16 residuals
__device__ __forceinline__ unsigned pack2l(float a, float b) {
    float ra = a - __half2float(__float2half_rn(a));
    float rb = b - __half2float(__float2half_rn(b));
    __half2 v = __floats2half2_rn(ra, rb);
    return *(unsigned*)&v;
}

// ------------------------- small prep kernels -----------------------------
__global__ void wprep_kernel(const float* __restrict__ W1,
                             const float* __restrict__ W2,
                             const float* __restrict__ W3) {
    int idx = blockIdx.x * 256 + threadIdx.x;
    if (idx < KA * Hv) {
        int j = idx / Hv, c = idx % Hv;
        float v = (j < 456) ? W1[(Hv + j) * Hv + c] : 0.0f;
        g_W1f[idx] = __float2half_rn(v);
    } else if (idx < KA * Hv + Hv * Hv) {
        int i2 = idx - KA * Hv;
        g_W2f[i2] = __float2half_rn(W2[i2]);
    } else if (idx < KA * Hv + 2 * Hv * Hv) {
        int i3 = idx - KA * Hv - Hv * Hv;
        g_W3f[i3] = __float2half_rn(W3[i3]);
    }
}

// node-term bias: bias1[site][c] = b1[c] + sum_r hV[site,r] * W1[r,c]  (exact fp32)
__global__ __launch_bounds__(128) void bias1_kernel(const float* __restrict__ hV,
                                                    const float* __restrict__ W1,
                                                    const float* __restrict__ b1) {
    extern __shared__ float bsm[];
    float* sW = bsm;
    float* shv = bsm + 16384;
    int c = threadIdx.x;
    for (int i = c; i < 16384; i += 128) sW[i] = W1[i];
    __syncthreads();
    for (int site = blockIdx.x; site < NSITE; site += gridDim.x) {
        shv[c] = hV[(size_t)site * Hv + c];
        __syncthreads();
        float acc = b1[c];
        #pragma unroll 8
        for (int r = 0; r < Hv; r++) acc = fmaf(shv[r], sW[r * Hv + c], acc);
        g_bias1[(size_t)site * Hv + c] = acc;
        __syncthreads();
    }
}

__device__ __forceinline__ void make_frame(const float* __restrict__ x,
                                           float* __restrict__ R,
                                           float* __restrict__ t) {
    float Nx = x[0], Ny = x[1], Nz = x[2];
    float CAx = x[3], CAy = x[4], CAz = x[5];
    float Cx = x[6], Cy = x[7], Cz = x[8];
    float e0x = CAx - Nx, e0y = CAy - Ny, e0z = CAz - Nz;
    float inv = 1.0f / sqrtf(e0x * e0x + e0y * e0y + e0z * e0z + EPSv);
    e0x *= inv; e0y *= inv; e0z *= inv;
    float e1x = Cx - CAx, e1y = Cy - CAy, e1z = Cz - CAz;
    float d = e0x * e1x + e0y * e1y + e0z * e1z;
    e1x -= e0x * d; e1y -= e0y * d; e1z -= e0z * d;
    inv = 1.0f / sqrtf(e1x * e1x + e1y * e1y + e1z * e1z + EPSv);
    e1x *= inv; e1y *= inv; e1z *= inv;
    float e2x = e0y * e1z - e0z * e1y;
    float e2y = e0z * e1x - e0x * e1z;
    float e2z = e0x * e1y - e0y * e1x;
    R[0] = e0x; R[1] = e1x; R[2] = e2x;
    R[3] = e0y; R[4] = e1y; R[5] = e2y;
    R[6] = e0z; R[7] = e1z; R[8] = e2z;
    t[0] = CAx; t[1] = CAy; t[2] = CAz;
}

// ---------------------------------------------------------------------------
// geoFeat: 2 sites per block, 256 threads; shared Wp stage.
// per-half layout (floats): hvp 3870 | pln 720 | R 270 | T 90 | npg 720 | feat 2160
// ---------------------------------------------------------------------------
#define GH_HVP  0
#define GH_PLN  3870
#define GH_R    4590
#define GH_T    4860
#define GH_NPG  4950
#define GH_FEAT 5670
#define GH_SIZE 7830
#define GEOF_SMEM ((3072 + 2 * GH_SIZE) * 4)   // 74928 bytes

__global__ void __launch_bounds__(256) geoFeat_kernel(
    const float* __restrict__ hE,
    const float* __restrict__ Xn,
    const float* __restrict__ Wp,
    const float* __restrict__ bp)
{
    extern __shared__ float gs[];
    int tid = threadIdx.x;
    int hf = tid >> 7, t = tid & 127;
    int site = blockIdx.x * 2 + hf;

    float* WP = gs;
    float* base = gs + 3072 + hf * GH_SIZE;

    for (int i = tid; i < 3072; i += 256) WP[i] = Wp[i];
    for (int i = t; i < 30 * 128; i += 128) {
        int k = i >> 7, j = i & 127;
        base[GH_HVP + k * 129 + j] = hE[((size_t)(site * Kv + k)) * NINv + 256 + j];
    }
    if (t < Kv) make_frame(Xn + ((size_t)(site * Kv + t)) * 9,
                           base + GH_R + t * 9, base + GH_T + t * 3);
    __syncthreads();

    // p_ln[30][24]
    if (t < 120) {
        int k = t % 30, g = t / 30;
        float acc[6];
        #pragma unroll
        for (int j = 0; j < 6; j++) acc[j] = bp[g * 6 + j];
        const float* e = base + GH_HVP + k * 129;
        const float* wbase = WP + g * 6;
        #pragma unroll 4
        for (int i = 0; i < 128; i++) {
            float h = e[i];
            const float* wr = wbase + i * 24;
            float2 w01 = *(const float2*)(wr);
            float2 w23 = *(const float2*)(wr + 2);
            float2 w45 = *(const float2*)(wr + 4);
            acc[0] = fmaf(h, w01.x, acc[0]);
            acc[1] = fmaf(h, w01.y, acc[1]);
            acc[2] = fmaf(h, w23.x, acc[2]);
            acc[3] = fmaf(h, w23.y, acc[3]);
            acc[4] = fmaf(h, w45.x, acc[4]);
            acc[5] = fmaf(h, w45.y, acc[5]);
        }
        #pragma unroll
        for (int j = 0; j < 6; j++) base[GH_PLN + k * 24 + g * 6 + j] = acc[j];
    }
    __syncthreads();

    if (t < Kv) {
        int k = t;
        const float* R = base + GH_R + k * 9;
        const float* tt = base + GH_T + k * 3;
        const float* pl = base + GH_PLN + k * 24;
        #pragma unroll
        for (int n = 0; n < 8; n++)
            #pragma unroll
            for (int i = 0; i < 3; i++)
                base[GH_NPG + k * 24 + n * 3 + i] =
                    tt[i] + R[i * 3] * pl[n * 3] + R[i * 3 + 1] * pl[n * 3 + 1]
                          + R[i * 3 + 2] * pl[n * 3 + 2];
    }
    __syncthreads();

    if (t < Kv) {
        int k = t;
        float* f = base + GH_FEAT + k * 72;
        const float* pl0 = base + GH_PLN;
        const float* pg  = base + GH_NPG;
        const float* R0  = base + GH_R;
        const float* t0  = base + GH_T;
        const float* ng  = base + GH_NPG + k * 24;
        #pragma unroll
        for (int n = 0; n < 8; n++) {
            float p0 = pl0[n * 3], p1 = pl0[n * 3 + 1], p2 = pl0[n * 3 + 2];
            f[n * 3] = p0; f[n * 3 + 1] = p1; f[n * 3 + 2] = p2;
            f[24 + n] = sqrtf(p0 * p0 + p1 * p1 + p2 * p2 + EPSv);
            float d0 = ng[n * 3]     - t0[0];
            float d1 = ng[n * 3 + 1] - t0[1];
            float d2 = ng[n * 3 + 2] - t0[2];
            float n0 = R0[0] * d0 + R0[3] * d1 + R0[6] * d2;
            float n1 = R0[1] * d0 + R0[4] * d1 + R0[7] * d2;
            float n2 = R0[2] * d0 + R0[5] * d1 + R0[8] * d2;
            f[32 + n * 3] = n0; f[32 + n * 3 + 1] = n1; f[32 + n * 3 + 2] = n2;
            f[56 + n] = sqrtf(n0 * n0 + n1 * n1 + n2 * n2 + EPSv);
            float gx = pg[n * 3]     - ng[n * 3];
            float gy = pg[n * 3 + 1] - ng[n * 3 + 1];
            float gz = pg[n * 3 + 2] - ng[n * 3 + 2];
            f[64 + n] = sqrtf(gx * gx + gy * gy + gz * gz + EPSv);
        }
    }
    __syncthreads();

    for (int i = t; i < 30 * 96; i += 128) {
        int k = i / 96, col = i - k * 96;
        float v = (col < 72) ? base[GH_FEAT + k * 72 + col] : 0.0f;
        g_feat[((size_t)(site * 32 + k)) * 96 + col] = v;
    }
}

// ---------------------------------------------------------------------------
// Fused GEMM, fp16 2-pass: A split fp16 (hi+lo), weights single fp16.
// C3 = gelu(gelu(A@W1+bias1)@W2+b2)@W3 + b3.
// 256 thr, M-tile 128 = 4 sites x 32 padded edges, 2 CTAs/SM.
// smem: Abuf 2x20480 [0,40960) | Wst 2x8704 [40960,58368) | spill 32768
//       W2/W3 (34816 ea) reuse [0,34816) after phase 1 / phase 2.
// ---------------------------------------------------------------------------
#define ABUF(i)  ((i) * 20480)
#define WST(i)   (40960 + (i) * 8704)
#define OFF_W    0
#define OFF_SPILL 58368
#define GEMM_SMEM (OFF_SPILL + 32768)   // 91136

__device__ __forceinline__ void cpasync16(unsigned dst, const void* src) {
    asm volatile("cp.async.cg.shared.global [%0], [%1], 16;\n" :: "r"(dst), "l"(src));
}
__device__ __forceinline__ void ldm_x4(unsigned* r, unsigned addr) {
    asm volatile("ldmatrix.sync.aligned.m8n8.x4.shared.b16 {%0,%1,%2,%3}, [%4];"
        : "=r"(r[0]), "=r"(r[1]), "=r"(r[2]), "=r"(r[3]) : "r"(addr));
}
__device__ __forceinline__ void ldm_x4_t(unsigned* r, unsigned addr) {
    asm volatile("ldmatrix.sync.aligned.m8n8.x4.trans.shared.b16 {%0,%1,%2,%3}, [%4];"
        : "=r"(r[0]), "=r"(r[1]), "=r"(r[2]), "=r"(r[3]) : "r"(addr));
}
__device__ __forceinline__ void mma_f16(float* d, const unsigned* a, unsigned b0, unsigned b1) {
    asm volatile("mma.sync.aligned.m16n8k16.row.col.f32.f16.f16.f32 "
        "{%0,%1,%2,%3}, {%4,%5,%6,%7}, {%8,%9}, {%0,%1,%2,%3};"
        : "+f"(d[0]), "+f"(d[1]), "+f"(d[2]), "+f"(d[3])
        : "r"(a[0]), "r"(a[1]), "r"(a[2]), "r"(a[3]), "r"(b0), "r"(b1));
}
__device__ __forceinline__ void sts128(unsigned addr, const unsigned* v) {
    asm volatile("st.shared.v4.b32 [%0], {%1,%2,%3,%4};"
        :: "r"(addr), "r"(v[0]), "r"(v[1]), "r"(v[2]), "r"(v[3]));
}
__device__ __forceinline__ void lds128(unsigned* v, unsigned addr) {
    asm volatile("ld.shared.v4.b32 {%0,%1,%2,%3}, [%4];"
        : "=r"(v[0]), "=r"(v[1]), "=r"(v[2]), "=r"(v[3]) : "r"(addr));
}

// W1 k-chunk loader: 32 rows of W1f into WST(st) (stride 136 halves)
__device__ __forceinline__ void wload_chunk(unsigned sbase, int st,
                                            const __half* __restrict__ W1f,
                                            int kc, int tid) {
    unsigned wst = sbase + WST(st);
    #pragma unroll
    for (int i = 0; i < 2; i++) {
        int tt = tid + i * 256;
        int rb = tt >> 4, sg = tt & 15;
        cpasync16(wst + (rb * 136 + sg * 8) * 2, W1f + (size_t)(kc + rb) * Hv + sg * 8);
    }
    asm volatile("cp.async.commit_group;\n" ::);
}

// Full 128x128 fp16 weight into [off, off+34816)
__device__ __forceinline__ void load_weight(unsigned sbase, unsigned off,
                                            const __half* __restrict__ src, int tid) {
    #pragma unroll
    for (int i = 0; i < 8; i++) {
        int idx = tid + i * 256;
        int r = idx >> 4, s = idx & 15;
        cpasync16(sbase + off + (r * 136 + s * 8) * 2, src + (size_t)r * Hv + s * 8);
    }
}

__global__ __launch_bounds__(256, 2) void fusedgemm_kernel(
    const float* __restrict__ hE, const float* __restrict__ feat,
    const __half* __restrict__ W1f, const __half* __restrict__ W2f,
    const __half* __restrict__ W3f,
    const float* __restrict__ bias1,
    const float* __restrict__ b2, const float* __restrict__ b3,
    float* __restrict__ C3)
{
    extern __shared__ __align__(16) unsigned char gsm[];
    unsigned sbase = (unsigned)__cvta_generic_to_shared(gsm);

    int tid = threadIdx.x;
    int lane = tid & 31, w = tid >> 5;
    int rowBase = blockIdx.x * 128;
    unsigned spill_base = sbase + OFF_SPILL + w * 4096 + lane * 16;

    // A loader identity: thread covers row arow, 16 cols at half16*16
    int arow = tid >> 1, half16 = tid & 1;
    int gr = rowBase + arow;
    int asite = gr >> 5;
    int ak = gr & 31; if (ak > 29) ak = 29;
    const float* hE_row = hE + ((size_t)(asite * Kv + ak)) * NINv + half16 * 16;
    const float* ft_row = feat + ((size_t)(asite * 32 + ak)) * 96 + half16 * 16;

    float4 f0, f1, f2, f3;
    #define LDA(cc) do { \
        const float4* s4 = (const float4*)(((cc) < 12) ? (hE_row + (cc) * 32) \
                                                       : (ft_row + ((cc) - 12) * 32)); \
        f0 = s4[0]; f1 = s4[1]; f2 = s4[2]; f3 = s4[3]; \
    } while (0)

    #define CVTSTS(buf) do { \
        unsigned uh[8], ul[8]; \
        uh[0] = pack2h(f0.x, f0.y); ul[0] = pack2l(f0.x, f0.y); \
        uh[1] = pack2h(f0.z, f0.w); ul[1] = pack2l(f0.z, f0.w); \
        uh[2] = pack2h(f1.x, f1.y); ul[2] = pack2l(f1.x, f1.y); \
        uh[3] = pack2h(f1.z, f1.w); ul[3] = pack2l(f1.z, f1.w); \
        uh[4] = pack2h(f2.x, f2.y); ul[4] = pack2l(f2.x, f2.y); \
        uh[5] = pack2h(f2.z, f2.w); ul[5] = pack2l(f2.z, f2.w); \
        uh[6] = pack2h(f3.x, f3.y); ul[6] = pack2l(f3.x, f3.y); \
        uh[7] = pack2h(f3.z, f3.w); ul[7] = pack2l(f3.z, f3.w); \
        unsigned ab = sbase + ABUF(buf) + (unsigned)((arow * 40 + half16 * 16) * 2); \
        sts128(ab, uh); sts128(ab + 16, uh + 4); \
        sts128(ab + 10240, ul); sts128(ab + 10240 + 16, ul + 4); \
    } while (0)

    float acc[16][4];
    #pragma unroll
    for (int t = 0; t < 16; t++)
        #pragma unroll
        for (int q = 0; q < 4; q++) acc[t][q] = 0.0f;

    // prologue
    wload_chunk(sbase, 0, W1f, 0, tid);
    wload_chunk(sbase, 1, W1f, 32, tid);
    LDA(0);
    CVTSTS(0);

    // -------- phase 1: A @ W1, K=480, fp16 2-pass --------
    for (int c = 0; c < NCH; c++) {
        if (c + 1 < NCH) { asm volatile("cp.async.wait_group 1;\n" ::); }
        else             { asm volatile("cp.async.wait_group 0;\n" ::); }
        __syncthreads();

        if (c + 1 < NCH) LDA(c + 1);

        unsigned abuf = sbase + ABUF(c & 1);
        unsigned wst  = sbase + WST(c & 1);
        #pragma unroll
        for (int kk = 0; kk < 32; kk += 16) {
            unsigned aH[4], aL[4];
            {
                int row = w * 16 + (lane & 15);
                unsigned off = (unsigned)((row * 40 + kk + ((lane >> 4) << 3)) * 2);
                ldm_x4(aH, abuf + off);
                ldm_x4(aL, abuf + 10240 + off);
            }
            #pragma unroll
            for (int nb = 0; nb < 8; nb++) {
                unsigned offb = (unsigned)(((kk + (lane & 15)) * 136 + nb * 16 + ((lane >> 4) << 3)) * 2);
                unsigned bh[4];
                ldm_x4_t(bh, wst + offb);
                mma_f16(acc[2 * nb],     aH, bh[0], bh[1]);
                mma_f16(acc[2 * nb],     aL, bh[0], bh[1]);
                mma_f16(acc[2 * nb + 1], aH, bh[2], bh[3]);
                mma_f16(acc[2 * nb + 1], aL, bh[2], bh[3]);
            }
        }

        if (c + 1 < NCH) CVTSTS((c + 1) & 1);
        __syncthreads();
        if (c + 2 < NCH) wload_chunk(sbase, c & 1, W1f, (c + 2) * 32, tid);
    }

    // W2 into [0, 34816) — A buffers dead now
    load_weight(sbase, OFF_W, W2f, tid);
    asm volatile("cp.async.commit_group;\n" ::);

    // phase-1 epilogue: + bias1(site), gelu, split (lows -> smem spill)
    int r0 = w * 16 + (lane >> 2);
    int r1 = r0 + 8;
    const float* bs0 = bias1 + (size_t)((rowBase + r0) >> 5) * Hv;
    const float* bs1 = bias1 + (size_t)((rowBase + r1) >> 5) * Hv;

    unsigned a_h[16][2];
    #pragma unroll
    for (int q = 0; q < 8; q++) {
        unsigned lo[4];
        #pragma unroll
        for (int h2 = 0; h2 < 2; h2++) {
            int t = 2 * q + h2;
            int col = t * 8 + ((lane & 3) << 1);
            float2 c0 = *(const float2*)(bs0 + col);
            float2 c1 = *(const float2*)(bs1 + col);
            float v00 = geluf(acc[t][0] + c0.x);
            float v01 = geluf(acc[t][1] + c0.y);
            float v10 = geluf(acc[t][2] + c1.x);
            float v11 = geluf(acc[t][3] + c1.y);
            a_h[t][0] = pack2h(v00, v01);
            lo[h2 * 2]     = pack2l(v00, v01);
            a_h[t][1] = pack2h(v10, v11);
            lo[h2 * 2 + 1] = pack2l(v10, v11);
            acc[t][0] = 0.0f; acc[t][1] = 0.0f; acc[t][2] = 0.0f; acc[t][3] = 0.0f;
        }
        sts128(spill_base + q * 512, lo);
    }
    asm volatile("cp.async.wait_group 0;\n" ::);
    __syncthreads();

    // -------- phase 2: C1 @ W2 (fp16 2-pass) --------
    #pragma unroll
    for (int q = 0; q < 8; q++) {
        unsigned aH[4] = { a_h[2 * q][0], a_h[2 * q][1], a_h[2 * q + 1][0], a_h[2 * q + 1][1] };
        unsigned aL[4];
        lds128(aL, spill_base + q * 512);
        #pragma unroll
        for (int nb = 0; nb < 8; nb++) {
            unsigned offb = (unsigned)(((q * 16 + (lane & 15)) * 136 + nb * 16 + ((lane >> 4) << 3)) * 2);
            unsigned bh[4];
            ldm_x4_t(bh, sbase + OFF_W + offb);
            mma_f16(acc[2 * nb],     aH, bh[0], bh[1]);
            mma_f16(acc[2 * nb],     aL, bh[0], bh[1]);
            mma_f16(acc[2 * nb + 1], aH, bh[2], bh[3]);
            mma_f16(acc[2 * nb + 1], aL, bh[2], bh[3]);
        }
    }
    __syncthreads();   // all warps done reading W2
    load_weight(sbase, OFF_W, W3f, tid);
    asm volatile("cp.async.commit_group;\n" ::);

    // phase-2 epilogue: + b2, gelu, split
    #pragma unroll
    for (int q = 0; q < 8; q++) {
        unsigned lo[4];
        #pragma unroll
        for (int h2 = 0; h2 < 2; h2++) {
            int t = 2 * q + h2;
            int col = t * 8 + ((lane & 3) << 1);
            float2 bb = *(const float2*)(b2 + col);
            float v00 = geluf(acc[t][0] + bb.x);
            float v01 = geluf(acc[t][1] + bb.y);
            float v10 = geluf(acc[t][2] + bb.x);
            float v11 = geluf(acc[t][3] + bb.y);
            a_h[t][0] = pack2h(v00, v01);
            lo[h2 * 2]     = pack2l(v00, v01);
            a_h[t][1] = pack2h(v10, v11);
            lo[h2 * 2 + 1] = pack2l(v10, v11);
            acc[t][0] = 0.0f; acc[t][1] = 0.0f; acc[t][2] = 0.0f; acc[t][3] = 0.0f;
        }
        sts128(spill_base + q * 512, lo);
    }
    asm volatile("cp.async.wait_group 0;\n" ::);
    __syncthreads();

    // -------- phase 3: C2 @ W3 (fp16 2-pass) --------
    #pragma unroll
    for (int q = 0; q < 8; q++) {
        unsigned aH[4] = { a_h[2 * q][0], a_h[2 * q][1], a_h[2 * q + 1][0], a_h[2 * q + 1][1] };
        unsigned aL[4];
        lds128(aL, spill_base + q * 512);
        #pragma unroll
        for (int nb = 0; nb < 8; nb++) {
            unsigned offb = (unsigned)(((q * 16 + (lane & 15)) * 136 + nb * 16 + ((lane >> 4) << 3)) * 2);
            unsigned bh[4];
            ldm_x4_t(bh, sbase + OFF_W + offb);
            mma_f16(acc[2 * nb],     aH, bh[0], bh[1]);
            mma_f16(acc[2 * nb],     aL, bh[0], bh[1]);
            mma_f16(acc[2 * nb + 1], aH, bh[2], bh[3]);
            mma_f16(acc[2 * nb + 1], aL, bh[2], bh[3]);
        }
    }

    // final epilogue: + b3, store fp32 C3
    #pragma unroll
    for (int t = 0; t < 16; t++) {
        int col = t * 8 + ((lane & 3) << 1);
        float2 bb = *(const float2*)(b3 + col);
        float2 v0; v0.x = acc[t][0] + bb.x; v0.y = acc[t][1] + bb.y;
        float2 v1; v1.x = acc[t][2] + bb.x; v1.y = acc[t][3] + bb.y;
        *(float2*)(C3 + (size_t)(rowBase + r0) * Hv + col) = v0;
        *(float2*)(C3 + (size_t)(rowBase + r1) * Hv + col) = v1;
    }
    #undef LDA
    #undef CVTSTS
}

// ---------------------------------------------------------------------------
// Final: masked mean over k + LN1 + FFN + LN2 + masked out. 8 sites/block.
// ---------------------------------------------------------------------------
#define SPB 8
__global__ __launch_bounds__(128) void final_kernel(
    const float* __restrict__ hV, const float* __restrict__ maskV,
    const float* __restrict__ maskA,
    const float* __restrict__ Wi, const float* __restrict__ bi,
    const float* __restrict__ Wo, const float* __restrict__ bo,
    const float* __restrict__ g1, const float* __restrict__ be1,
    const float* __restrict__ g2, const float* __restrict__ be2,
    float* __restrict__ out)
{
    __shared__ float s_h[SPB][Hv];
    __shared__ float s_f[SPB][4 * Hv];
    __shared__ float s_red[8];
    int c = threadIdx.x;
    int base_site = blockIdx.x * SPB;

    for (int s = 0; s < SPB; s++) {
        int site = base_site + s;
        const float* c3 = g_C3 + (size_t)site * 32 * Hv + c;
        const float* ma = maskA + (size_t)site * Kv;
        float nm = 0.0f;
        #pragma unroll
        for (int k = 0; k < Kv; k++) nm += c3[k * Hv] * ma[k];
        nm *= (1.0f / (float)Kv);
        float xv = hV[(size_t)site * Hv + c] + nm;
        float sum = xv, sq = xv * xv;
        #pragma unroll
        for (int o = 16; o; o >>= 1) {
            sum += __shfl_xor_sync(0xffffffffu, sum, o);
            sq  += __shfl_xor_sync(0xffffffffu, sq, o);
        }
        if ((c & 31) == 0) { s_red[c >> 5] = sum; s_red[4 + (c >> 5)] = sq; }
        __syncthreads();
        sum = s_red[0] + s_red[1] + s_red[2] + s_red[3];
        sq  = s_red[4] + s_red[5] + s_red[6] + s_red[7];
        float mean = sum * (1.0f / Hv);
        float var  = sq * (1.0f / Hv) - mean * mean;
        s_h[s][c] = (xv - mean) * rsqrtf(var + 1e-5f) * g1[c] + be1[c];
        __syncthreads();
    }

    float hi[SPB][4];
    #pragma unroll
    for (int s = 0; s < SPB; s++) {
        hi[s][0] = bi[c];        hi[s][1] = bi[c + 128];
        hi[s][2] = bi[c + 256];  hi[s][3] = bi[c + 384];
    }
    for (int r = 0; r < Hv; r++) {
        const float* wr = Wi + (size_t)r * 512;
        float w0 = wr[c], w1 = wr[c + 128], w2 = wr[c + 256], w3 = wr[c + 384];
        #pragma unroll
        for (int s = 0; s < SPB; s++) {
            float hv = s_h[s][r];
            hi[s][0] = fmaf(hv, w0, hi[s][0]);
            hi[s][1] = fmaf(hv, w1, hi[s][1]);
            hi[s][2] = fmaf(hv, w2, hi[s][2]);
            hi[s][3] = fmaf(hv, w3, hi[s][3]);
        }
    }
    #pragma unroll
    for (int s = 0; s < SPB; s++) {
        s_f[s][c]       = geluf(hi[s][0]);
        s_f[s][c + 128] = geluf(hi[s][1]);
        s_f[s][c + 256] = geluf(hi[s][2]);
        s_f[s][c + 384] = geluf(hi[s][3]);
    }
    __syncthreads();

    float d[SPB];
    #pragma unroll
    for (int s = 0; s < SPB; s++) d[s] = bo[c];
    for (int j = 0; j < 512; j++) {
        float w = Wo[(size_t)j * Hv + c];
        #pragma unroll
        for (int s = 0; s < SPB; s++) d[s] = fmaf(s_f[s][j], w, d[s]);
    }

    for (int s = 0; s < SPB; s++) {
        int site = base_site + s;
        float x2 = s_h[s][c] + d[s];
        float sum = x2, sq = x2 * x2;
        #pragma unroll
        for (int o = 16; o; o >>= 1) {
            sum += __shfl_xor_sync(0xffffffffu, sum, o);
            sq  += __shfl_xor_sync(0xffffffffu, sq, o);
        }
        if ((c & 31) == 0) { s_red[c >> 5] = sum; s_red[4 + (c >> 5)] = sq; }
        __syncthreads();
        sum = s_red[0] + s_red[1] + s_red[2] + s_red[3];
        sq  = s_red[4] + s_red[5] + s_red[6] + s_red[7];
        float mean = sum * (1.0f / Hv);
        float var  = sq * (1.0f / Hv) - mean * mean;
        float h2 = (x2 - mean) * rsqrtf(var + 1e-5f) * g2[c] + be2[c];
        out[(size_t)site * Hv + c] = maskV[site] * h2;
        __syncthreads();
    }
}

// ---------------------------------------------------------------------------

extern "C" void kernel_launch(void* const* d_in, const int* in_sizes, int n_in,
                              void* d_out, int out_size) {
    const float* hV    = (const float*)d_in[0];
    const float* hE    = (const float*)d_in[1];
    const float* Xn    = (const float*)d_in[3];
    const float* maskV = (const float*)d_in[4];
    const float* maskA = (const float*)d_in[5];
    const float* Wp    = (const float*)d_in[6];
    const float* bp    = (const float*)d_in[7];
    const float* W1    = (const float*)d_in[8];
    const float* b1    = (const float*)d_in[9];
    const float* W2    = (const float*)d_in[10];
    const float* b2    = (const float*)d_in[11];
    const float* W3    = (const float*)d_in[12];
    const float* b3    = (const float*)d_in[13];
    const float* Wi    = (const float*)d_in[14];
    const float* bi    = (const float*)d_in[15];
    const float* Wo    = (const float*)d_in[16];
    const float* bo    = (const float*)d_in[17];
    const float* g1    = (const float*)d_in[18];
    const float* be1   = (const float*)d_in[19];
    const float* g2    = (const float*)d_in[20];
    const float* be2   = (const float*)d_in[21];
    float* out = (float*)d_out;

    cudaFuncSetAttribute(fusedgemm_kernel, cudaFuncAttributeMaxDynamicSharedMemorySize, GEMM_SMEM);
    cudaFuncSetAttribute(bias1_kernel, cudaFuncAttributeMaxDynamicSharedMemorySize, 66048);
    cudaFuncSetAttribute(geoFeat_kernel, cudaFuncAttributeMaxDynamicSharedMemorySize, GEOF_SMEM);

    static void *pFeat = nullptr, *pC3, *pB1, *pW1f, *pW2f, *pW3f;
    if (!pFeat) {
        cudaGetSymbolAddress(&pFeat, g_feat);
        cudaGetSymbolAddress(&pC3, g_C3);   cudaGetSymbolAddress(&pB1, g_bias1);
        cudaGetSymbolAddress(&pW1f, g_W1f);
        cudaGetSymbolAddress(&pW2f, g_W2f);
        cudaGetSymbolAddress(&pW3f, g_W3f);
    }

    wprep_kernel<<<(KA * Hv + 2 * Hv * Hv + 255) / 256, 256>>>(W1, W2, W3);
    bias1_kernel<<<512, 128, 66048>>>(hV, W1, b1);
    geoFeat_kernel<<<NSITE / 2, 256, GEOF_SMEM>>>(hE, Xn, Wp, bp);

    fusedgemm_kernel<<<MPAD / 128, 256, GEMM_SMEM>>>(
        hE, (const float*)pFeat,
        (const __half*)pW1f, (const __half*)pW2f, (const __half*)pW3f,
        (const float*)pB1, b2, b3, (float*)pC3);

    final_kernel<<<NSITE / SPB, 128>>>(hV, maskV, maskA, Wi, bi, Wo, bo,
                                       g1, be1, g2, be2, out);
}